// round 9
// baseline (speedup 1.0000x reference)
#include <cuda_runtime.h>
#include <cuda_bf16.h>
#include <math.h>
#include <stdint.h>

// ============================================================================
// LocalAttention via split-bf16 warp-level MMA (mma.sync m16n8k16).
//   split x,W -> hi/lo bf16
//   Q = x@Wq^T, K = x@Wk^T, Vt = Wv@x^T      (NT GEMM, split epilogue)
//   attn = softmax(mask ? -1e9 : Q@K^T * s)   (NT GEMM, mask epi; fp32)
//   softmax also emits P hi/lo bf16
//   cntx = P @ Vt^T                           (NT GEMM, fp32 epi)
// GEMM v2: block 128x256, 8 warps, warp tile 64x64, 2-stage cp.async.
// Output: [cntx (N*D) | attn (N*N)].  Mask is int32.
// ============================================================================

#define AN 8192
#define AD 512

// ---- device-global scratch (allocation-free rule) ----
__device__ __nv_bfloat16 g_xh [(size_t)AN * AD], g_xl [(size_t)AN * AD];
__device__ __nv_bfloat16 g_Wqh[(size_t)AD * AD], g_Wql[(size_t)AD * AD];
__device__ __nv_bfloat16 g_Wkh[(size_t)AD * AD], g_Wkl[(size_t)AD * AD];
__device__ __nv_bfloat16 g_Wvh[(size_t)AD * AD], g_Wvl[(size_t)AD * AD];
__device__ __nv_bfloat16 g_Qh [(size_t)AN * AD], g_Ql [(size_t)AN * AD];
__device__ __nv_bfloat16 g_Kh [(size_t)AN * AD], g_Kl [(size_t)AN * AD];
__device__ __nv_bfloat16 g_Vth[(size_t)AD * AN], g_Vtl[(size_t)AD * AN];
__device__ __nv_bfloat16 g_Ph [(size_t)AN * (size_t)AN], g_Pl [(size_t)AN * (size_t)AN];
__device__ float         g_S  [(size_t)AN * (size_t)AN];   // fallback attn scratch

// ---------------------------------------------------------------------------
// helpers
// ---------------------------------------------------------------------------
__device__ __forceinline__ uint32_t smem_u32(const void* p) {
    uint32_t a;
    asm("{ .reg .u64 t; cvta.to.shared.u64 t, %1; cvt.u32.u64 %0, t; }"
        : "=r"(a) : "l"(p));
    return a;
}
__device__ __forceinline__ void cp16(uint32_t dst, const void* src) {
    asm volatile("cp.async.cg.shared.global [%0], [%1], 16;" :: "r"(dst), "l"(src));
}
#define CP_COMMIT() asm volatile("cp.async.commit_group;" ::: "memory")
#define CP_WAIT(N)  asm volatile("cp.async.wait_group %0;" :: "n"(N) : "memory")

__device__ __forceinline__ void ldsm_x4(uint32_t* r, uint32_t addr) {
    asm volatile("ldmatrix.sync.aligned.m8n8.x4.shared.b16 {%0,%1,%2,%3}, [%4];"
                 : "=r"(r[0]), "=r"(r[1]), "=r"(r[2]), "=r"(r[3]) : "r"(addr));
}
__device__ __forceinline__ void mma16816(float* d, const uint32_t* a, const uint32_t* b) {
    asm volatile(
        "mma.sync.aligned.m16n8k16.row.col.f32.bf16.bf16.f32 "
        "{%0,%1,%2,%3}, {%4,%5,%6,%7}, {%8,%9}, {%0,%1,%2,%3};"
        : "+f"(d[0]), "+f"(d[1]), "+f"(d[2]), "+f"(d[3])
        : "r"(a[0]), "r"(a[1]), "r"(a[2]), "r"(a[3]), "r"(b[0]), "r"(b[1]));
}
__device__ __forceinline__ void split1(float v, __nv_bfloat16& h, __nv_bfloat16& l) {
    h = __float2bfloat16_rn(v);
    l = __float2bfloat16_rn(v - __bfloat162float(h));
}

// ---------------------------------------------------------------------------
// split kernel: fp32 -> (hi, lo) bf16
// ---------------------------------------------------------------------------
__global__ __launch_bounds__(256)
void split_f32(const float* __restrict__ in, __nv_bfloat16* __restrict__ hi,
               __nv_bfloat16* __restrict__ lo, int n4)
{
    int i = blockIdx.x * 256 + threadIdx.x;
    if (i >= n4) return;
    float4 v = *(const float4*)(in + (size_t)i * 4);
    __nv_bfloat16 h0, h1, h2, h3, l0, l1, l2, l3;
    split1(v.x, h0, l0); split1(v.y, h1, l1);
    split1(v.z, h2, l2); split1(v.w, h3, l3);
    *(__nv_bfloat162*)(hi + (size_t)i * 4)     = __nv_bfloat162(h0, h1);
    *(__nv_bfloat162*)(hi + (size_t)i * 4 + 2) = __nv_bfloat162(h2, h3);
    *(__nv_bfloat162*)(lo + (size_t)i * 4)     = __nv_bfloat162(l0, l1);
    *(__nv_bfloat162*)(lo + (size_t)i * 4 + 2) = __nv_bfloat162(l2, l3);
}

// ---------------------------------------------------------------------------
// NT split-bf16 GEMM v2: C[M,Nn] = (Ah+Al)[M,K] * (Bh+Bl)[Nn,K]^T
// Block 128x256x32, 256 threads (8 warps, warp tile 64x64), 2-stage cp.async.
// EPI: 0 = split bf16 out (Chi/Clo), 1 = mask+scale fp32, 2 = fp32
// smem row stride 80B: conflict-free ldmatrix.
// ---------------------------------------------------------------------------
#define RS    80
#define A_MAT (128 * RS)                    // 10240 B
#define B_MAT (256 * RS)                    // 20480 B
#define STAGEB (2 * A_MAT + 2 * B_MAT)      // 61440 B
#define SMEM_TOT (2 * STAGEB)               // 122880 B

template <int EPI>
__global__ __launch_bounds__(256)
void hgemm_nt(const __nv_bfloat16* __restrict__ Ah, const __nv_bfloat16* __restrict__ Al,
              const __nv_bfloat16* __restrict__ Bh, const __nv_bfloat16* __restrict__ Bl,
              int M, int Nn, int K,
              float* __restrict__ Cf,
              __nv_bfloat16* __restrict__ Chi, __nv_bfloat16* __restrict__ Clo,
              const int* __restrict__ mask, float scale)
{
    extern __shared__ char smem[];
    const uint32_t sb = smem_u32(smem);
    const int tid = threadIdx.x;
    const int wid = tid >> 5, lid = tid & 31;
    const int mBase = blockIdx.y * 128;
    const int nBase = blockIdx.x * 256;
    const int mW = (wid & 1) * 64;       // warp m offset (0,64)
    const int nW = (wid >> 1) * 64;      // warp n offset (0,64,128,192)

    const __nv_bfloat16* gA[2] = { Ah + (size_t)mBase * K, Al + (size_t)mBase * K };
    const __nv_bfloat16* gB[2] = { Bh + (size_t)nBase * K, Bl + (size_t)nBase * K };

    float acc[4][8][4];
#pragma unroll
    for (int i = 0; i < 4; i++)
#pragma unroll
        for (int j = 0; j < 8; j++)
#pragma unroll
            for (int v = 0; v < 4; v++) acc[i][j][v] = 0.f;

    const int ntiles = K / 32;

    auto load_tile = [&](int kt, int s) {
        const int k0 = kt * 32;
        const uint32_t st = sb + s * STAGEB;
        // A: 128 rows x 32 k, hi+lo (512 chunks each)
#pragma unroll
        for (int j = 0; j < 2; ++j) {
            int c = tid + j * 256;
            int row = c >> 2, ch = c & 3;
            size_t go = (size_t)row * K + k0 + ch * 8;
            uint32_t so = row * RS + ch * 16;
            cp16(st + 0 * A_MAT + so, gA[0] + go);
            cp16(st + 1 * A_MAT + so, gA[1] + go);
        }
        // B: 256 rows x 32 k, hi+lo (1024 chunks each)
#pragma unroll
        for (int j = 0; j < 4; ++j) {
            int c = tid + j * 256;
            int row = c >> 2, ch = c & 3;
            size_t go = (size_t)row * K + k0 + ch * 8;
            uint32_t so = row * RS + ch * 16;
            cp16(st + 2 * A_MAT + so,         gB[0] + go);
            cp16(st + 2 * A_MAT + B_MAT + so, gB[1] + go);
        }
        CP_COMMIT();
    };

    load_tile(0, 0);

    for (int kt = 0; kt < ntiles; ++kt) {
        if (kt + 1 < ntiles) {
            load_tile(kt + 1, (kt + 1) & 1);
            CP_WAIT(1);
        } else {
            CP_WAIT(0);
        }
        __syncthreads();

        const uint32_t st = sb + (kt & 1) * STAGEB;

#pragma unroll
        for (int s = 0; s < 2; ++s) {
            uint32_t ah[4][4], al[4][4], bh[8][2], bl[8][2];
            // A: m16k16 frags, rows mW+f*16+(lid&15), k-half by lid>>4
            const uint32_t kbA = s * 32 + ((lid >> 4) * 16);
#pragma unroll
            for (int f = 0; f < 4; ++f) {
                uint32_t ra = st + (mW + f * 16 + (lid & 15)) * RS + kbA;
                ldsm_x4(ah[f], ra);
                ldsm_x4(al[f], ra + A_MAT);
            }
            // B: x4 = two n8 frags; rows nW+f*16+(lid>>4)*8+(lid&7), k-half by (lid>>3)&1
            const uint32_t rowB = ((lid >> 4) * 8) + (lid & 7);
            const uint32_t kbB = s * 32 + (((lid >> 3) & 1) * 16);
#pragma unroll
            for (int f = 0; f < 4; ++f) {
                uint32_t rb = st + 2 * A_MAT + (nW + f * 16 + rowB) * RS + kbB;
                ldsm_x4(&bh[2 * f][0], rb);
                ldsm_x4(&bl[2 * f][0], rb + B_MAT);
            }
#pragma unroll
            for (int mf = 0; mf < 4; ++mf)
#pragma unroll
                for (int nf = 0; nf < 8; ++nf) {
                    mma16816(acc[mf][nf], ah[mf], bh[nf]);
                    mma16816(acc[mf][nf], ah[mf], bl[nf]);
                    mma16816(acc[mf][nf], al[mf], bh[nf]);
                }
        }
        __syncthreads();
    }

    // ---- epilogue ----
    const int r0b = mBase + mW + (lid >> 2);
    const int c0b = nBase + nW + (lid & 3) * 2;
#pragma unroll
    for (int mf = 0; mf < 4; ++mf) {
#pragma unroll
        for (int nf = 0; nf < 8; ++nf) {
            const float* d = acc[mf][nf];
#pragma unroll
            for (int h = 0; h < 2; ++h) {
                int row = r0b + mf * 16 + h * 8;
                int col = c0b + nf * 8;
                size_t o = (size_t)row * Nn + col;
                float v0 = d[h * 2 + 0], v1 = d[h * 2 + 1];
                if (EPI == 0) {
                    __nv_bfloat16 h0, h1, l0, l1;
                    split1(v0, h0, l0); split1(v1, h1, l1);
                    *(__nv_bfloat162*)(Chi + o) = __nv_bfloat162(h0, h1);
                    *(__nv_bfloat162*)(Clo + o) = __nv_bfloat162(l0, l1);
                } else if (EPI == 1) {
                    int2 mv = *(const int2*)(mask + o);
                    float2 w;
                    w.x = mv.x ? -1e9f : v0 * scale;
                    w.y = mv.y ? -1e9f : v1 * scale;
                    *(float2*)(Cf + o) = w;
                } else {
                    *(float2*)(Cf + o) = make_float2(v0, v1);
                }
            }
        }
    }
}

// ---------------------------------------------------------------------------
// Row softmax (in place, fp32) + emit P hi/lo bf16.
// ---------------------------------------------------------------------------
__global__ __launch_bounds__(256)
void softmax_rows(float* __restrict__ S, __nv_bfloat16* __restrict__ Ph,
                  __nv_bfloat16* __restrict__ Pl, int n)
{
    extern __shared__ float row[];
    __shared__ float red[33];

    const int tid = threadIdx.x;
    float* p = S + (size_t)blockIdx.x * n;
    __nv_bfloat16* ph = Ph + (size_t)blockIdx.x * n;
    __nv_bfloat16* pl = Pl + (size_t)blockIdx.x * n;

    float m = -INFINITY;
    for (int i = tid * 4; i < n; i += 1024) {
        float4 v = *(const float4*)(p + i);
        *(float4*)(row + i) = v;
        m = fmaxf(m, fmaxf(fmaxf(v.x, v.y), fmaxf(v.z, v.w)));
    }
#pragma unroll
    for (int o = 16; o; o >>= 1) m = fmaxf(m, __shfl_xor_sync(~0u, m, o));
    if ((tid & 31) == 0) red[tid >> 5] = m;
    __syncthreads();
    if (tid < 32) {
        float v = (tid < 8) ? red[tid] : -INFINITY;
#pragma unroll
        for (int o = 4; o; o >>= 1) v = fmaxf(v, __shfl_xor_sync(~0u, v, o));
        if (tid == 0) red[32] = v;
    }
    __syncthreads();
    m = red[32];

    float s = 0.f;
    for (int i = tid * 4; i < n; i += 1024) {
        float4 v = *(float4*)(row + i);
        v.x = __expf(v.x - m); v.y = __expf(v.y - m);
        v.z = __expf(v.z - m); v.w = __expf(v.w - m);
        s += (v.x + v.y) + (v.z + v.w);
        *(float4*)(row + i) = v;
    }
    __syncthreads();
#pragma unroll
    for (int o = 16; o; o >>= 1) s += __shfl_xor_sync(~0u, s, o);
    if ((tid & 31) == 0) red[tid >> 5] = s;
    __syncthreads();
    if (tid < 32) {
        float v = (tid < 8) ? red[tid] : 0.f;
#pragma unroll
        for (int o = 4; o; o >>= 1) v += __shfl_xor_sync(~0u, v, o);
        if (tid == 0) red[32] = v;
    }
    __syncthreads();
    const float inv = 1.f / red[32];

    for (int i = tid * 4; i < n; i += 1024) {
        float4 v = *(float4*)(row + i);
        v.x *= inv; v.y *= inv; v.z *= inv; v.w *= inv;
        *(float4*)(p + i) = v;
        __nv_bfloat16 h0, h1, h2, h3, l0, l1, l2, l3;
        split1(v.x, h0, l0); split1(v.y, h1, l1);
        split1(v.z, h2, l2); split1(v.w, h3, l3);
        *(__nv_bfloat162*)(ph + i)     = __nv_bfloat162(h0, h1);
        *(__nv_bfloat162*)(ph + i + 2) = __nv_bfloat162(h2, h3);
        *(__nv_bfloat162*)(pl + i)     = __nv_bfloat162(l0, l1);
        *(__nv_bfloat162*)(pl + i + 2) = __nv_bfloat162(l2, l3);
    }
}

// ---------------------------------------------------------------------------
// Launch
// ---------------------------------------------------------------------------
extern "C" void kernel_launch(void* const* d_in, const int* in_sizes, int n_in,
                              void* d_out, int out_size)
{
    const float* x    = (const float*)d_in[0];
    const int*   mask = (const int*)d_in[1];
    const float* Wq   = (const float*)d_in[2];
    const float* Wk   = (const float*)d_in[3];
    const float* Wv   = (const float*)d_in[4];
    float* out = (float*)d_out;

    __nv_bfloat16 *xh, *xl, *Wqh, *Wql, *Wkh, *Wkl, *Wvh, *Wvl;
    __nv_bfloat16 *Qh, *Ql, *Kh, *Kl, *Vth, *Vtl, *Ph, *Pl;
    cudaGetSymbolAddress((void**)&xh,  g_xh);  cudaGetSymbolAddress((void**)&xl,  g_xl);
    cudaGetSymbolAddress((void**)&Wqh, g_Wqh); cudaGetSymbolAddress((void**)&Wql, g_Wql);
    cudaGetSymbolAddress((void**)&Wkh, g_Wkh); cudaGetSymbolAddress((void**)&Wkl, g_Wkl);
    cudaGetSymbolAddress((void**)&Wvh, g_Wvh); cudaGetSymbolAddress((void**)&Wvl, g_Wvl);
    cudaGetSymbolAddress((void**)&Qh,  g_Qh);  cudaGetSymbolAddress((void**)&Ql,  g_Ql);
    cudaGetSymbolAddress((void**)&Kh,  g_Kh);  cudaGetSymbolAddress((void**)&Kl,  g_Kl);
    cudaGetSymbolAddress((void**)&Vth, g_Vth); cudaGetSymbolAddress((void**)&Vtl, g_Vtl);
    cudaGetSymbolAddress((void**)&Ph,  g_Ph);  cudaGetSymbolAddress((void**)&Pl,  g_Pl);

    const size_t nd = (size_t)AN * AD;
    const size_t nn = (size_t)AN * AN;
    float* cntx = out;
    float* attn = out + nd;
    if ((size_t)out_size < nd + nn)
        cudaGetSymbolAddress((void**)&attn, g_S);

    const float scale = 1.0f / sqrtf((float)AD);

    cudaFuncSetAttribute(hgemm_nt<0>, cudaFuncAttributeMaxDynamicSharedMemorySize, SMEM_TOT);
    cudaFuncSetAttribute(hgemm_nt<1>, cudaFuncAttributeMaxDynamicSharedMemorySize, SMEM_TOT);
    cudaFuncSetAttribute(hgemm_nt<2>, cudaFuncAttributeMaxDynamicSharedMemorySize, SMEM_TOT);

    // 1) split inputs
    split_f32<<<(AN * AD / 4 + 255) / 256, 256>>>(x,  xh,  xl,  AN * AD / 4);
    split_f32<<<(AD * AD / 4 + 255) / 256, 256>>>(Wq, Wqh, Wql, AD * AD / 4);
    split_f32<<<(AD * AD / 4 + 255) / 256, 256>>>(Wk, Wkh, Wkl, AD * AD / 4);
    split_f32<<<(AD * AD / 4 + 255) / 256, 256>>>(Wv, Wvh, Wvl, AD * AD / 4);

    // 2) projections (split epilogue)  [grid = (Nn/256, M/128)]
    dim3 gP(AD / 256, AN / 128);
    hgemm_nt<0><<<gP, 256, SMEM_TOT>>>(xh, xl, Wqh, Wql, AN, AD, AD,
                                       nullptr, Qh, Ql, nullptr, 1.f);
    hgemm_nt<0><<<gP, 256, SMEM_TOT>>>(xh, xl, Wkh, Wkl, AN, AD, AD,
                                       nullptr, Kh, Kl, nullptr, 1.f);
    dim3 gV(AN / 256, AD / 128);
    hgemm_nt<0><<<gV, 256, SMEM_TOT>>>(Wvh, Wvl, xh, xl, AD, AN, AD,
                                       nullptr, Vth, Vtl, nullptr, 1.f);

    // 3) scores (mask epilogue, fp32)
    dim3 gS(AN / 256, AN / 128);
    hgemm_nt<1><<<gS, 256, SMEM_TOT>>>(Qh, Ql, Kh, Kl, AN, AN, AD,
                                       attn, nullptr, nullptr, mask, scale);

    // 4) softmax (+ P hi/lo)
    softmax_rows<<<AN, 256, AN * sizeof(float)>>>(attn, Ph, Pl, AN);

    // 5) context (fp32 epilogue)
    dim3 gC(AD / 256, AN / 128);
    hgemm_nt<2><<<gC, 256, SMEM_TOT>>>(Ph, Pl, Vth, Vtl, AN, AD, AN,
                                       cntx, nullptr, nullptr, nullptr, 1.f);
}

// round 10
// speedup vs baseline: 1.0631x; 1.0631x over previous
#include <cuda_runtime.h>
#include <cuda_bf16.h>
#include <math.h>
#include <stdint.h>

// ============================================================================
// LocalAttention via split-bf16 warp-level MMA (mma.sync m16n8k16).
//   split x,W -> hi/lo bf16
//   Q = x@Wq^T, K = x@Wk^T, Vt = Wv@x^T      (NT GEMM, split epilogue)
//   attn = softmax(mask ? -1e9 : Q@K^T * s)   (NT GEMM, mask epi; fp32)
//   softmax also emits P hi/lo bf16
//   cntx = P @ Vt^T                           (NT GEMM, fp32 epi)
// GEMM v3: block 128x128x32, 512 threads (16 warps, warp tile 32x32),
// 2-stage cp.async, XOR-swizzled 64B smem rows (64KB smem, ~90 regs).
// Output: [cntx (N*D) | attn (N*N)].  Mask is int32.
// ============================================================================

#define AN 8192
#define AD 512

// ---- device-global scratch (allocation-free rule) ----
__device__ __nv_bfloat16 g_xh [(size_t)AN * AD], g_xl [(size_t)AN * AD];
__device__ __nv_bfloat16 g_Wqh[(size_t)AD * AD], g_Wql[(size_t)AD * AD];
__device__ __nv_bfloat16 g_Wkh[(size_t)AD * AD], g_Wkl[(size_t)AD * AD];
__device__ __nv_bfloat16 g_Wvh[(size_t)AD * AD], g_Wvl[(size_t)AD * AD];
__device__ __nv_bfloat16 g_Qh [(size_t)AN * AD], g_Ql [(size_t)AN * AD];
__device__ __nv_bfloat16 g_Kh [(size_t)AN * AD], g_Kl [(size_t)AN * AD];
__device__ __nv_bfloat16 g_Vth[(size_t)AD * AN], g_Vtl[(size_t)AD * AN];
__device__ __nv_bfloat16 g_Ph [(size_t)AN * (size_t)AN], g_Pl [(size_t)AN * (size_t)AN];
__device__ float         g_S  [(size_t)AN * (size_t)AN];   // fallback attn scratch

// ---------------------------------------------------------------------------
// helpers
// ---------------------------------------------------------------------------
__device__ __forceinline__ uint32_t smem_u32(const void* p) {
    uint32_t a;
    asm("{ .reg .u64 t; cvta.to.shared.u64 t, %1; cvt.u32.u64 %0, t; }"
        : "=r"(a) : "l"(p));
    return a;
}
__device__ __forceinline__ void cp16(uint32_t dst, const void* src) {
    asm volatile("cp.async.cg.shared.global [%0], [%1], 16;" :: "r"(dst), "l"(src));
}
#define CP_COMMIT() asm volatile("cp.async.commit_group;" ::: "memory")
#define CP_WAIT(N)  asm volatile("cp.async.wait_group %0;" :: "n"(N) : "memory")

__device__ __forceinline__ void ldsm_x4(uint32_t* r, uint32_t addr) {
    asm volatile("ldmatrix.sync.aligned.m8n8.x4.shared.b16 {%0,%1,%2,%3}, [%4];"
                 : "=r"(r[0]), "=r"(r[1]), "=r"(r[2]), "=r"(r[3]) : "r"(addr));
}
__device__ __forceinline__ void mma16816(float* d, const uint32_t* a, const uint32_t* b) {
    asm volatile(
        "mma.sync.aligned.m16n8k16.row.col.f32.bf16.bf16.f32 "
        "{%0,%1,%2,%3}, {%4,%5,%6,%7}, {%8,%9}, {%0,%1,%2,%3};"
        : "+f"(d[0]), "+f"(d[1]), "+f"(d[2]), "+f"(d[3])
        : "r"(a[0]), "r"(a[1]), "r"(a[2]), "r"(a[3]), "r"(b[0]), "r"(b[1]));
}
__device__ __forceinline__ void split1(float v, __nv_bfloat16& h, __nv_bfloat16& l) {
    h = __float2bfloat16_rn(v);
    l = __float2bfloat16_rn(v - __bfloat162float(h));
}

// XOR swizzle: 64B rows, 16B chunks; phys chunk = c ^ ((row>>1)&3).
// Verified: all 8 addresses of an ldmatrix phase distinct mod 128 -> no conflicts.
__device__ __forceinline__ uint32_t swz(uint32_t row, uint32_t c) {
    return row * 64 + ((c ^ ((row >> 1) & 3)) << 4);
}

// ---------------------------------------------------------------------------
// split kernel: fp32 -> (hi, lo) bf16
// ---------------------------------------------------------------------------
__global__ __launch_bounds__(256)
void split_f32(const float* __restrict__ in, __nv_bfloat16* __restrict__ hi,
               __nv_bfloat16* __restrict__ lo, int n4)
{
    int i = blockIdx.x * 256 + threadIdx.x;
    if (i >= n4) return;
    float4 v = *(const float4*)(in + (size_t)i * 4);
    __nv_bfloat16 h0, h1, h2, h3, l0, l1, l2, l3;
    split1(v.x, h0, l0); split1(v.y, h1, l1);
    split1(v.z, h2, l2); split1(v.w, h3, l3);
    *(__nv_bfloat162*)(hi + (size_t)i * 4)     = __nv_bfloat162(h0, h1);
    *(__nv_bfloat162*)(hi + (size_t)i * 4 + 2) = __nv_bfloat162(h2, h3);
    *(__nv_bfloat162*)(lo + (size_t)i * 4)     = __nv_bfloat162(l0, l1);
    *(__nv_bfloat162*)(lo + (size_t)i * 4 + 2) = __nv_bfloat162(l2, l3);
}

// ---------------------------------------------------------------------------
// NT split-bf16 GEMM v3: C[M,Nn] = (Ah+Al)[M,K] * (Bh+Bl)[Nn,K]^T
// Block 128x128x32, 512 threads, warp tile 32x32 (4x4 warps), 2-stage.
// EPI: 0 = split bf16 out (Chi/Clo), 1 = mask+scale fp32, 2 = fp32
// ---------------------------------------------------------------------------
#define MATB   (128 * 64)                  // 8192 B per matrix (128 rows x 64B)
#define STAGEB (4 * MATB)                  // 32768 B (Ah|Al|Bh|Bl)
#define SMEM_TOT (2 * STAGEB)              // 65536 B

template <int EPI>
__global__ __launch_bounds__(512)
void hgemm_nt(const __nv_bfloat16* __restrict__ Ah, const __nv_bfloat16* __restrict__ Al,
              const __nv_bfloat16* __restrict__ Bh, const __nv_bfloat16* __restrict__ Bl,
              int M, int Nn, int K,
              float* __restrict__ Cf,
              __nv_bfloat16* __restrict__ Chi, __nv_bfloat16* __restrict__ Clo,
              const int* __restrict__ mask, float scale)
{
    extern __shared__ char smem[];
    const uint32_t sb = smem_u32(smem);
    const int tid = threadIdx.x;
    const int wid = tid >> 5, lid = tid & 31;
    const int mBase = blockIdx.y * 128;
    const int nBase = blockIdx.x * 128;
    const int mW = (wid & 3) * 32;       // warp m offset (0..96)
    const int nW = (wid >> 2) * 32;      // warp n offset (0..96)

    const __nv_bfloat16* gA[2] = { Ah + (size_t)mBase * K, Al + (size_t)mBase * K };
    const __nv_bfloat16* gB[2] = { Bh + (size_t)nBase * K, Bl + (size_t)nBase * K };

    float acc[2][4][4];
#pragma unroll
    for (int i = 0; i < 2; i++)
#pragma unroll
        for (int j = 0; j < 4; j++)
#pragma unroll
            for (int v = 0; v < 4; v++) acc[i][j][v] = 0.f;

    const int ntiles = K / 32;

    // 512 threads, 1 chunk per matrix each: row = tid>>2, chunk = tid&3
    const int ldRow = tid >> 2, ldC = tid & 3;
    const uint32_t ldOff = swz(ldRow, ldC);
    auto load_tile = [&](int kt, int s) {
        const size_t go = (size_t)ldRow * K + kt * 32 + ldC * 8;
        const uint32_t st = sb + s * STAGEB;
        cp16(st + 0 * MATB + ldOff, gA[0] + go);
        cp16(st + 1 * MATB + ldOff, gA[1] + go);
        cp16(st + 2 * MATB + ldOff, gB[0] + go);
        cp16(st + 3 * MATB + ldOff, gB[1] + go);
        CP_COMMIT();
    };

    load_tile(0, 0);

    for (int kt = 0; kt < ntiles; ++kt) {
        if (kt + 1 < ntiles) {
            load_tile(kt + 1, (kt + 1) & 1);
            CP_WAIT(1);
        } else {
            CP_WAIT(0);
        }
        __syncthreads();

        const uint32_t st = sb + (kt & 1) * STAGEB;

#pragma unroll
        for (int s = 0; s < 2; ++s) {
            uint32_t ah[2][4], al[2][4], bh[4][2], bl[4][2];
            // A: rows mW + f*16 + (lid&15), k-chunk = s*2 + (lid>>4)
            const uint32_t cA = s * 2 + (lid >> 4);
#pragma unroll
            for (int f = 0; f < 2; ++f) {
                uint32_t ra = st + swz(mW + f * 16 + (lid & 15), cA);
                ldsm_x4(ah[f], ra);
                ldsm_x4(al[f], ra + MATB);
            }
            // B: rows nW + f*16 + (lid>>4)*8 + (lid&7), k-chunk = s*2 + ((lid>>3)&1)
            const uint32_t rowB = ((lid >> 4) * 8) + (lid & 7);
            const uint32_t cB = s * 2 + ((lid >> 3) & 1);
#pragma unroll
            for (int f = 0; f < 2; ++f) {
                uint32_t rb = st + 2 * MATB + swz(nW + f * 16 + rowB, cB);
                ldsm_x4(&bh[2 * f][0], rb);
                ldsm_x4(&bl[2 * f][0], rb + MATB);
            }
#pragma unroll
            for (int mf = 0; mf < 2; ++mf)
#pragma unroll
                for (int nf = 0; nf < 4; ++nf) {
                    mma16816(acc[mf][nf], ah[mf], bh[nf]);
                    mma16816(acc[mf][nf], ah[mf], bl[nf]);
                    mma16816(acc[mf][nf], al[mf], bh[nf]);
                }
        }
        __syncthreads();
    }

    // ---- epilogue ----
    const int r0b = mBase + mW + (lid >> 2);
    const int c0b = nBase + nW + (lid & 3) * 2;
#pragma unroll
    for (int mf = 0; mf < 2; ++mf) {
#pragma unroll
        for (int nf = 0; nf < 4; ++nf) {
            const float* d = acc[mf][nf];
#pragma unroll
            for (int h = 0; h < 2; ++h) {
                int row = r0b + mf * 16 + h * 8;
                int col = c0b + nf * 8;
                size_t o = (size_t)row * Nn + col;
                float v0 = d[h * 2 + 0], v1 = d[h * 2 + 1];
                if (EPI == 0) {
                    __nv_bfloat16 h0, h1, l0, l1;
                    split1(v0, h0, l0); split1(v1, h1, l1);
                    *(__nv_bfloat162*)(Chi + o) = __nv_bfloat162(h0, h1);
                    *(__nv_bfloat162*)(Clo + o) = __nv_bfloat162(l0, l1);
                } else if (EPI == 1) {
                    int2 mv = *(const int2*)(mask + o);
                    float2 w;
                    w.x = mv.x ? -1e9f : v0 * scale;
                    w.y = mv.y ? -1e9f : v1 * scale;
                    *(float2*)(Cf + o) = w;
                } else {
                    *(float2*)(Cf + o) = make_float2(v0, v1);
                }
            }
        }
    }
}

// ---------------------------------------------------------------------------
// Row softmax (in place, fp32) + emit P hi/lo bf16.
// ---------------------------------------------------------------------------
__global__ __launch_bounds__(256)
void softmax_rows(float* __restrict__ S, __nv_bfloat16* __restrict__ Ph,
                  __nv_bfloat16* __restrict__ Pl, int n)
{
    extern __shared__ float row[];
    __shared__ float red[33];

    const int tid = threadIdx.x;
    float* p = S + (size_t)blockIdx.x * n;
    __nv_bfloat16* ph = Ph + (size_t)blockIdx.x * n;
    __nv_bfloat16* pl = Pl + (size_t)blockIdx.x * n;

    float m = -INFINITY;
    for (int i = tid * 4; i < n; i += 1024) {
        float4 v = *(const float4*)(p + i);
        *(float4*)(row + i) = v;
        m = fmaxf(m, fmaxf(fmaxf(v.x, v.y), fmaxf(v.z, v.w)));
    }
#pragma unroll
    for (int o = 16; o; o >>= 1) m = fmaxf(m, __shfl_xor_sync(~0u, m, o));
    if ((tid & 31) == 0) red[tid >> 5] = m;
    __syncthreads();
    if (tid < 32) {
        float v = (tid < 8) ? red[tid] : -INFINITY;
#pragma unroll
        for (int o = 4; o; o >>= 1) v = fmaxf(v, __shfl_xor_sync(~0u, v, o));
        if (tid == 0) red[32] = v;
    }
    __syncthreads();
    m = red[32];

    float s = 0.f;
    for (int i = tid * 4; i < n; i += 1024) {
        float4 v = *(float4*)(row + i);
        v.x = __expf(v.x - m); v.y = __expf(v.y - m);
        v.z = __expf(v.z - m); v.w = __expf(v.w - m);
        s += (v.x + v.y) + (v.z + v.w);
        *(float4*)(row + i) = v;
    }
    __syncthreads();
#pragma unroll
    for (int o = 16; o; o >>= 1) s += __shfl_xor_sync(~0u, s, o);
    if ((tid & 31) == 0) red[tid >> 5] = s;
    __syncthreads();
    if (tid < 32) {
        float v = (tid < 8) ? red[tid] : 0.f;
#pragma unroll
        for (int o = 4; o; o >>= 1) v += __shfl_xor_sync(~0u, v, o);
        if (tid == 0) red[32] = v;
    }
    __syncthreads();
    const float inv = 1.f / red[32];

    for (int i = tid * 4; i < n; i += 1024) {
        float4 v = *(float4*)(row + i);
        v.x *= inv; v.y *= inv; v.z *= inv; v.w *= inv;
        *(float4*)(p + i) = v;
        __nv_bfloat16 h0, h1, h2, h3, l0, l1, l2, l3;
        split1(v.x, h0, l0); split1(v.y, h1, l1);
        split1(v.z, h2, l2); split1(v.w, h3, l3);
        *(__nv_bfloat162*)(ph + i)     = __nv_bfloat162(h0, h1);
        *(__nv_bfloat162*)(ph + i + 2) = __nv_bfloat162(h2, h3);
        *(__nv_bfloat162*)(pl + i)     = __nv_bfloat162(l0, l1);
        *(__nv_bfloat162*)(pl + i + 2) = __nv_bfloat162(l2, l3);
    }
}

// ---------------------------------------------------------------------------
// Launch
// ---------------------------------------------------------------------------
extern "C" void kernel_launch(void* const* d_in, const int* in_sizes, int n_in,
                              void* d_out, int out_size)
{
    const float* x    = (const float*)d_in[0];
    const int*   mask = (const int*)d_in[1];
    const float* Wq   = (const float*)d_in[2];
    const float* Wk   = (const float*)d_in[3];
    const float* Wv   = (const float*)d_in[4];
    float* out = (float*)d_out;

    __nv_bfloat16 *xh, *xl, *Wqh, *Wql, *Wkh, *Wkl, *Wvh, *Wvl;
    __nv_bfloat16 *Qh, *Ql, *Kh, *Kl, *Vth, *Vtl, *Ph, *Pl;
    cudaGetSymbolAddress((void**)&xh,  g_xh);  cudaGetSymbolAddress((void**)&xl,  g_xl);
    cudaGetSymbolAddress((void**)&Wqh, g_Wqh); cudaGetSymbolAddress((void**)&Wql, g_Wql);
    cudaGetSymbolAddress((void**)&Wkh, g_Wkh); cudaGetSymbolAddress((void**)&Wkl, g_Wkl);
    cudaGetSymbolAddress((void**)&Wvh, g_Wvh); cudaGetSymbolAddress((void**)&Wvl, g_Wvl);
    cudaGetSymbolAddress((void**)&Qh,  g_Qh);  cudaGetSymbolAddress((void**)&Ql,  g_Ql);
    cudaGetSymbolAddress((void**)&Kh,  g_Kh);  cudaGetSymbolAddress((void**)&Kl,  g_Kl);
    cudaGetSymbolAddress((void**)&Vth, g_Vth); cudaGetSymbolAddress((void**)&Vtl, g_Vtl);
    cudaGetSymbolAddress((void**)&Ph,  g_Ph);  cudaGetSymbolAddress((void**)&Pl,  g_Pl);

    const size_t nd = (size_t)AN * AD;
    const size_t nn = (size_t)AN * AN;
    float* cntx = out;
    float* attn = out + nd;
    if ((size_t)out_size < nd + nn)
        cudaGetSymbolAddress((void**)&attn, g_S);

    const float scale = 1.0f / sqrtf((float)AD);

    cudaFuncSetAttribute(hgemm_nt<0>, cudaFuncAttributeMaxDynamicSharedMemorySize, SMEM_TOT);
    cudaFuncSetAttribute(hgemm_nt<1>, cudaFuncAttributeMaxDynamicSharedMemorySize, SMEM_TOT);
    cudaFuncSetAttribute(hgemm_nt<2>, cudaFuncAttributeMaxDynamicSharedMemorySize, SMEM_TOT);

    // 1) split inputs
    split_f32<<<(AN * AD / 4 + 255) / 256, 256>>>(x,  xh,  xl,  AN * AD / 4);
    split_f32<<<(AD * AD / 4 + 255) / 256, 256>>>(Wq, Wqh, Wql, AD * AD / 4);
    split_f32<<<(AD * AD / 4 + 255) / 256, 256>>>(Wk, Wkh, Wkl, AD * AD / 4);
    split_f32<<<(AD * AD / 4 + 255) / 256, 256>>>(Wv, Wvh, Wvl, AD * AD / 4);

    // 2) projections (split epilogue)  [grid = (Nn/128, M/128)]
    dim3 gP(AD / 128, AN / 128);
    hgemm_nt<0><<<gP, 512, SMEM_TOT>>>(xh, xl, Wqh, Wql, AN, AD, AD,
                                       nullptr, Qh, Ql, nullptr, 1.f);
    hgemm_nt<0><<<gP, 512, SMEM_TOT>>>(xh, xl, Wkh, Wkl, AN, AD, AD,
                                       nullptr, Kh, Kl, nullptr, 1.f);
    dim3 gV(AN / 128, AD / 128);
    hgemm_nt<0><<<gV, 512, SMEM_TOT>>>(Wvh, Wvl, xh, xl, AD, AN, AD,
                                       nullptr, Vth, Vtl, nullptr, 1.f);

    // 3) scores (mask epilogue, fp32)
    dim3 gS(AN / 128, AN / 128);
    hgemm_nt<1><<<gS, 512, SMEM_TOT>>>(Qh, Ql, Kh, Kl, AN, AN, AD,
                                       attn, nullptr, nullptr, mask, scale);

    // 4) softmax (+ P hi/lo)
    softmax_rows<<<AN, 256, AN * sizeof(float)>>>(attn, Ph, Pl, AN);

    // 5) context (fp32 epilogue)
    dim3 gC(AD / 128, AN / 128);
    hgemm_nt<2><<<gC, 512, SMEM_TOT>>>(Ph, Pl, Vth, Vtl, AN, AD, AN,
                                       cntx, nullptr, nullptr, nullptr, 1.f);
}

// round 11
// speedup vs baseline: 1.1786x; 1.1086x over previous
#include <cuda_runtime.h>
#include <cuda_bf16.h>
#include <math.h>
#include <stdint.h>

// ============================================================================
// LocalAttention via split-bf16 warp-level MMA (mma.sync m16n8k16).
//   split x,W -> hi/lo bf16
//   Q = x@Wq^T, K = x@Wk^T, Vt = Wv@x^T      (NT GEMM, split epilogue)
//   attn = softmax(mask ? -1e9 : Q@K^T * s)   (NT GEMM, mask epi; fp32)
//   softmax also emits P hi/lo bf16
//   cntx = P @ Vt^T                           (NT GEMM, fp32 epi)
// GEMM v4: block 128x128x64, 512 threads (16 warps, warp tile 32x32),
// 2-stage cp.async (128KB smem), 128B-row XOR swizzle, half the barriers of v3.
// Output: [cntx (N*D) | attn (N*N)].  Mask is int32.
// ============================================================================

#define AN 8192
#define AD 512

// ---- device-global scratch (allocation-free rule) ----
__device__ __nv_bfloat16 g_xh [(size_t)AN * AD], g_xl [(size_t)AN * AD];
__device__ __nv_bfloat16 g_Wqh[(size_t)AD * AD], g_Wql[(size_t)AD * AD];
__device__ __nv_bfloat16 g_Wkh[(size_t)AD * AD], g_Wkl[(size_t)AD * AD];
__device__ __nv_bfloat16 g_Wvh[(size_t)AD * AD], g_Wvl[(size_t)AD * AD];
__device__ __nv_bfloat16 g_Qh [(size_t)AN * AD], g_Ql [(size_t)AN * AD];
__device__ __nv_bfloat16 g_Kh [(size_t)AN * AD], g_Kl [(size_t)AN * AD];
__device__ __nv_bfloat16 g_Vth[(size_t)AD * AN], g_Vtl[(size_t)AD * AN];
__device__ __nv_bfloat16 g_Ph [(size_t)AN * (size_t)AN], g_Pl [(size_t)AN * (size_t)AN];
__device__ float         g_S  [(size_t)AN * (size_t)AN];   // fallback attn scratch

// ---------------------------------------------------------------------------
// helpers
// ---------------------------------------------------------------------------
__device__ __forceinline__ uint32_t smem_u32(const void* p) {
    uint32_t a;
    asm("{ .reg .u64 t; cvta.to.shared.u64 t, %1; cvt.u32.u64 %0, t; }"
        : "=r"(a) : "l"(p));
    return a;
}
__device__ __forceinline__ void cp16(uint32_t dst, const void* src) {
    asm volatile("cp.async.cg.shared.global [%0], [%1], 16;" :: "r"(dst), "l"(src));
}
#define CP_COMMIT() asm volatile("cp.async.commit_group;" ::: "memory")
#define CP_WAIT(N)  asm volatile("cp.async.wait_group %0;" :: "n"(N) : "memory")

__device__ __forceinline__ void ldsm_x4(uint32_t* r, uint32_t addr) {
    asm volatile("ldmatrix.sync.aligned.m8n8.x4.shared.b16 {%0,%1,%2,%3}, [%4];"
                 : "=r"(r[0]), "=r"(r[1]), "=r"(r[2]), "=r"(r[3]) : "r"(addr));
}
__device__ __forceinline__ void mma16816(float* d, const uint32_t* a, const uint32_t* b) {
    asm volatile(
        "mma.sync.aligned.m16n8k16.row.col.f32.bf16.bf16.f32 "
        "{%0,%1,%2,%3}, {%4,%5,%6,%7}, {%8,%9}, {%0,%1,%2,%3};"
        : "+f"(d[0]), "+f"(d[1]), "+f"(d[2]), "+f"(d[3])
        : "r"(a[0]), "r"(a[1]), "r"(a[2]), "r"(a[3]), "r"(b[0]), "r"(b[1]));
}
__device__ __forceinline__ void split1(float v, __nv_bfloat16& h, __nv_bfloat16& l) {
    h = __float2bfloat16_rn(v);
    l = __float2bfloat16_rn(v - __bfloat162float(h));
}

// 128B-row swizzle: 16B chunks c in 0..7, phys chunk = c ^ (row & 7).
// All 8 addresses of an ldmatrix phase (consecutive rows, same c) land in
// distinct 16B banks; cp.async stores (fixed row, distinct c) likewise.
__device__ __forceinline__ uint32_t swz(uint32_t row, uint32_t c) {
    return row * 128 + ((c ^ (row & 7)) << 4);
}

// ---------------------------------------------------------------------------
// split kernel: fp32 -> (hi, lo) bf16
// ---------------------------------------------------------------------------
__global__ __launch_bounds__(256)
void split_f32(const float* __restrict__ in, __nv_bfloat16* __restrict__ hi,
               __nv_bfloat16* __restrict__ lo, int n4)
{
    int i = blockIdx.x * 256 + threadIdx.x;
    if (i >= n4) return;
    float4 v = *(const float4*)(in + (size_t)i * 4);
    __nv_bfloat16 h0, h1, h2, h3, l0, l1, l2, l3;
    split1(v.x, h0, l0); split1(v.y, h1, l1);
    split1(v.z, h2, l2); split1(v.w, h3, l3);
    *(__nv_bfloat162*)(hi + (size_t)i * 4)     = __nv_bfloat162(h0, h1);
    *(__nv_bfloat162*)(hi + (size_t)i * 4 + 2) = __nv_bfloat162(h2, h3);
    *(__nv_bfloat162*)(lo + (size_t)i * 4)     = __nv_bfloat162(l0, l1);
    *(__nv_bfloat162*)(lo + (size_t)i * 4 + 2) = __nv_bfloat162(l2, l3);
}

// ---------------------------------------------------------------------------
// NT split-bf16 GEMM v4: C[M,Nn] = (Ah+Al)[M,K] * (Bh+Bl)[Nn,K]^T
// Block 128x128x64, 512 threads, warp tile 32x32 (4x4 warps), 2-stage.
// EPI: 0 = split bf16 out (Chi/Clo), 1 = mask+scale fp32, 2 = fp32
// ---------------------------------------------------------------------------
#define MATB   (128 * 128)                 // 16384 B per matrix (128 rows x 128B)
#define STAGEB (4 * MATB)                  // 65536 B (Ah|Al|Bh|Bl)
#define SMEM_TOT (2 * STAGEB)              // 131072 B

template <int EPI>
__global__ __launch_bounds__(512)
void hgemm_nt(const __nv_bfloat16* __restrict__ Ah, const __nv_bfloat16* __restrict__ Al,
              const __nv_bfloat16* __restrict__ Bh, const __nv_bfloat16* __restrict__ Bl,
              int M, int Nn, int K,
              float* __restrict__ Cf,
              __nv_bfloat16* __restrict__ Chi, __nv_bfloat16* __restrict__ Clo,
              const int* __restrict__ mask, float scale)
{
    extern __shared__ char smem[];
    const uint32_t sb = smem_u32(smem);
    const int tid = threadIdx.x;
    const int wid = tid >> 5, lid = tid & 31;
    const int mBase = blockIdx.y * 128;
    const int nBase = blockIdx.x * 128;
    const int mW = (wid & 3) * 32;       // warp m offset (0..96)
    const int nW = (wid >> 2) * 32;      // warp n offset (0..96)

    const __nv_bfloat16* gA[2] = { Ah + (size_t)mBase * K, Al + (size_t)mBase * K };
    const __nv_bfloat16* gB[2] = { Bh + (size_t)nBase * K, Bl + (size_t)nBase * K };

    float acc[2][4][4];
#pragma unroll
    for (int i = 0; i < 2; i++)
#pragma unroll
        for (int j = 0; j < 4; j++)
#pragma unroll
            for (int v = 0; v < 4; v++) acc[i][j][v] = 0.f;

    const int ntiles = K / 64;

    // 128 rows x 8 chunks = 1024 slots per matrix; 512 threads -> 2 slots each.
    auto load_tile = [&](int kt, int s) {
        const uint32_t st = sb + s * STAGEB;
#pragma unroll
        for (int j = 0; j < 2; ++j) {
            int slot = tid + j * 512;
            int row = slot >> 3, c = slot & 7;
            size_t go = (size_t)row * K + kt * 64 + c * 8;
            uint32_t so = swz(row, c);
            cp16(st + 0 * MATB + so, gA[0] + go);
            cp16(st + 1 * MATB + so, gA[1] + go);
            cp16(st + 2 * MATB + so, gB[0] + go);
            cp16(st + 3 * MATB + so, gB[1] + go);
        }
        CP_COMMIT();
    };

    load_tile(0, 0);

    for (int kt = 0; kt < ntiles; ++kt) {
        if (kt + 1 < ntiles) {
            load_tile(kt + 1, (kt + 1) & 1);
            CP_WAIT(1);
        } else {
            CP_WAIT(0);
        }
        __syncthreads();

        const uint32_t st = sb + (kt & 1) * STAGEB;

#pragma unroll
        for (int s = 0; s < 4; ++s) {       // 4 x k16 within the 64-k tile
            uint32_t ah[2][4], al[2][4], bh[4][2], bl[4][2];
            // A: rows mW + f*16 + (lid&15), chunk = s*2 + (lid>>4)
            const uint32_t cA = s * 2 + (lid >> 4);
#pragma unroll
            for (int f = 0; f < 2; ++f) {
                uint32_t ra = st + swz(mW + f * 16 + (lid & 15), cA);
                ldsm_x4(ah[f], ra);
                ldsm_x4(al[f], ra + MATB);
            }
            // B: rows nW + f*16 + (lid>>4)*8 + (lid&7), chunk = s*2 + ((lid>>3)&1)
            const uint32_t rowB = ((lid >> 4) * 8) + (lid & 7);
            const uint32_t cB = s * 2 + ((lid >> 3) & 1);
#pragma unroll
            for (int f = 0; f < 2; ++f) {
                uint32_t rb = st + 2 * MATB + swz(nW + f * 16 + rowB, cB);
                ldsm_x4(&bh[2 * f][0], rb);
                ldsm_x4(&bl[2 * f][0], rb + MATB);
            }
#pragma unroll
            for (int mf = 0; mf < 2; ++mf)
#pragma unroll
                for (int nf = 0; nf < 4; ++nf) {
                    mma16816(acc[mf][nf], ah[mf], bh[nf]);
                    mma16816(acc[mf][nf], ah[mf], bl[nf]);
                    mma16816(acc[mf][nf], al[mf], bh[nf]);
                }
        }
        __syncthreads();
    }

    // ---- epilogue ----
    const int r0b = mBase + mW + (lid >> 2);
    const int c0b = nBase + nW + (lid & 3) * 2;
#pragma unroll
    for (int mf = 0; mf < 2; ++mf) {
#pragma unroll
        for (int nf = 0; nf < 4; ++nf) {
            const float* d = acc[mf][nf];
#pragma unroll
            for (int h = 0; h < 2; ++h) {
                int row = r0b + mf * 16 + h * 8;
                int col = c0b + nf * 8;
                size_t o = (size_t)row * Nn + col;
                float v0 = d[h * 2 + 0], v1 = d[h * 2 + 1];
                if (EPI == 0) {
                    __nv_bfloat16 h0, h1, l0, l1;
                    split1(v0, h0, l0); split1(v1, h1, l1);
                    *(__nv_bfloat162*)(Chi + o) = __nv_bfloat162(h0, h1);
                    *(__nv_bfloat162*)(Clo + o) = __nv_bfloat162(l0, l1);
                } else if (EPI == 1) {
                    int2 mv = *(const int2*)(mask + o);
                    float2 w;
                    w.x = mv.x ? -1e9f : v0 * scale;
                    w.y = mv.y ? -1e9f : v1 * scale;
                    *(float2*)(Cf + o) = w;
                } else {
                    *(float2*)(Cf + o) = make_float2(v0, v1);
                }
            }
        }
    }
}

// ---------------------------------------------------------------------------
// Row softmax (in place, fp32) + emit P hi/lo bf16.
// ---------------------------------------------------------------------------
__global__ __launch_bounds__(256)
void softmax_rows(float* __restrict__ S, __nv_bfloat16* __restrict__ Ph,
                  __nv_bfloat16* __restrict__ Pl, int n)
{
    extern __shared__ float row[];
    __shared__ float red[33];

    const int tid = threadIdx.x;
    float* p = S + (size_t)blockIdx.x * n;
    __nv_bfloat16* ph = Ph + (size_t)blockIdx.x * n;
    __nv_bfloat16* pl = Pl + (size_t)blockIdx.x * n;

    float m = -INFINITY;
    for (int i = tid * 4; i < n; i += 1024) {
        float4 v = *(const float4*)(p + i);
        *(float4*)(row + i) = v;
        m = fmaxf(m, fmaxf(fmaxf(v.x, v.y), fmaxf(v.z, v.w)));
    }
#pragma unroll
    for (int o = 16; o; o >>= 1) m = fmaxf(m, __shfl_xor_sync(~0u, m, o));
    if ((tid & 31) == 0) red[tid >> 5] = m;
    __syncthreads();
    if (tid < 32) {
        float v = (tid < 8) ? red[tid] : -INFINITY;
#pragma unroll
        for (int o = 4; o; o >>= 1) v = fmaxf(v, __shfl_xor_sync(~0u, v, o));
        if (tid == 0) red[32] = v;
    }
    __syncthreads();
    m = red[32];

    float s = 0.f;
    for (int i = tid * 4; i < n; i += 1024) {
        float4 v = *(float4*)(row + i);
        v.x = __expf(v.x - m); v.y = __expf(v.y - m);
        v.z = __expf(v.z - m); v.w = __expf(v.w - m);
        s += (v.x + v.y) + (v.z + v.w);
        *(float4*)(row + i) = v;
    }
    __syncthreads();
#pragma unroll
    for (int o = 16; o; o >>= 1) s += __shfl_xor_sync(~0u, s, o);
    if ((tid & 31) == 0) red[tid >> 5] = s;
    __syncthreads();
    if (tid < 32) {
        float v = (tid < 8) ? red[tid] : 0.f;
#pragma unroll
        for (int o = 4; o; o >>= 1) v += __shfl_xor_sync(~0u, v, o);
        if (tid == 0) red[32] = v;
    }
    __syncthreads();
    const float inv = 1.f / red[32];

    for (int i = tid * 4; i < n; i += 1024) {
        float4 v = *(float4*)(row + i);
        v.x *= inv; v.y *= inv; v.z *= inv; v.w *= inv;
        *(float4*)(p + i) = v;
        __nv_bfloat16 h0, h1, h2, h3, l0, l1, l2, l3;
        split1(v.x, h0, l0); split1(v.y, h1, l1);
        split1(v.z, h2, l2); split1(v.w, h3, l3);
        *(__nv_bfloat162*)(ph + i)     = __nv_bfloat162(h0, h1);
        *(__nv_bfloat162*)(ph + i + 2) = __nv_bfloat162(h2, h3);
        *(__nv_bfloat162*)(pl + i)     = __nv_bfloat162(l0, l1);
        *(__nv_bfloat162*)(pl + i + 2) = __nv_bfloat162(l2, l3);
    }
}

// ---------------------------------------------------------------------------
// Launch
// ---------------------------------------------------------------------------
extern "C" void kernel_launch(void* const* d_in, const int* in_sizes, int n_in,
                              void* d_out, int out_size)
{
    const float* x    = (const float*)d_in[0];
    const int*   mask = (const int*)d_in[1];
    const float* Wq   = (const float*)d_in[2];
    const float* Wk   = (const float*)d_in[3];
    const float* Wv   = (const float*)d_in[4];
    float* out = (float*)d_out;

    __nv_bfloat16 *xh, *xl, *Wqh, *Wql, *Wkh, *Wkl, *Wvh, *Wvl;
    __nv_bfloat16 *Qh, *Ql, *Kh, *Kl, *Vth, *Vtl, *Ph, *Pl;
    cudaGetSymbolAddress((void**)&xh,  g_xh);  cudaGetSymbolAddress((void**)&xl,  g_xl);
    cudaGetSymbolAddress((void**)&Wqh, g_Wqh); cudaGetSymbolAddress((void**)&Wql, g_Wql);
    cudaGetSymbolAddress((void**)&Wkh, g_Wkh); cudaGetSymbolAddress((void**)&Wkl, g_Wkl);
    cudaGetSymbolAddress((void**)&Wvh, g_Wvh); cudaGetSymbolAddress((void**)&Wvl, g_Wvl);
    cudaGetSymbolAddress((void**)&Qh,  g_Qh);  cudaGetSymbolAddress((void**)&Ql,  g_Ql);
    cudaGetSymbolAddress((void**)&Kh,  g_Kh);  cudaGetSymbolAddress((void**)&Kl,  g_Kl);
    cudaGetSymbolAddress((void**)&Vth, g_Vth); cudaGetSymbolAddress((void**)&Vtl, g_Vtl);
    cudaGetSymbolAddress((void**)&Ph,  g_Ph);  cudaGetSymbolAddress((void**)&Pl,  g_Pl);

    const size_t nd = (size_t)AN * AD;
    const size_t nn = (size_t)AN * AN;
    float* cntx = out;
    float* attn = out + nd;
    if ((size_t)out_size < nd + nn)
        cudaGetSymbolAddress((void**)&attn, g_S);

    const float scale = 1.0f / sqrtf((float)AD);

    cudaFuncSetAttribute(hgemm_nt<0>, cudaFuncAttributeMaxDynamicSharedMemorySize, SMEM_TOT);
    cudaFuncSetAttribute(hgemm_nt<1>, cudaFuncAttributeMaxDynamicSharedMemorySize, SMEM_TOT);
    cudaFuncSetAttribute(hgemm_nt<2>, cudaFuncAttributeMaxDynamicSharedMemorySize, SMEM_TOT);

    // 1) split inputs
    split_f32<<<(AN * AD / 4 + 255) / 256, 256>>>(x,  xh,  xl,  AN * AD / 4);
    split_f32<<<(AD * AD / 4 + 255) / 256, 256>>>(Wq, Wqh, Wql, AD * AD / 4);
    split_f32<<<(AD * AD / 4 + 255) / 256, 256>>>(Wk, Wkh, Wkl, AD * AD / 4);
    split_f32<<<(AD * AD / 4 + 255) / 256, 256>>>(Wv, Wvh, Wvl, AD * AD / 4);

    // 2) projections (split epilogue)  [grid = (Nn/128, M/128)]
    dim3 gP(AD / 128, AN / 128);
    hgemm_nt<0><<<gP, 512, SMEM_TOT>>>(xh, xl, Wqh, Wql, AN, AD, AD,
                                       nullptr, Qh, Ql, nullptr, 1.f);
    hgemm_nt<0><<<gP, 512, SMEM_TOT>>>(xh, xl, Wkh, Wkl, AN, AD, AD,
                                       nullptr, Kh, Kl, nullptr, 1.f);
    dim3 gV(AN / 128, AD / 128);
    hgemm_nt<0><<<gV, 512, SMEM_TOT>>>(Wvh, Wvl, xh, xl, AD, AN, AD,
                                       nullptr, Vth, Vtl, nullptr, 1.f);

    // 3) scores (mask epilogue, fp32)
    dim3 gS(AN / 128, AN / 128);
    hgemm_nt<1><<<gS, 512, SMEM_TOT>>>(Qh, Ql, Kh, Kl, AN, AN, AD,
                                       attn, nullptr, nullptr, mask, scale);

    // 4) softmax (+ P hi/lo)
    softmax_rows<<<AN, 256, AN * sizeof(float)>>>(attn, Ph, Pl, AN);

    // 5) context (fp32 epilogue)
    dim3 gC(AD / 128, AN / 128);
    hgemm_nt<2><<<gC, 512, SMEM_TOT>>>(Ph, Pl, Vth, Vtl, AN, AD, AN,
                                       cntx, nullptr, nullptr, nullptr, 1.f);
}

// round 12
// speedup vs baseline: 1.2122x; 1.0285x over previous
#include <cuda_runtime.h>
#include <cuda_bf16.h>
#include <math.h>
#include <stdint.h>

// ============================================================================
// LocalAttention via split-bf16 warp-level MMA (mma.sync m16n8k16).
//   split x,W -> hi/lo bf16
//   Q = x@Wq^T, K = x@Wk^T, Vt = Wv@x^T      (NT GEMM, split epilogue)
//   attn = softmax(mask ? -1e9 : Q@K^T * s)   (NT GEMM, mask epi; fp32)
//   softmax also emits P hi/lo bf16
//   cntx = P @ Vt^T                           (NT GEMM, fp32 epi)
// GEMM v5: block 128x256x64, 512 threads (16 warps, warp tile 32x64),
// 2-stage cp.async (192KB smem), 128B-row XOR swizzle.
// Output: [cntx (N*D) | attn (N*N)].  Mask is int32.
// ============================================================================

#define AN 8192
#define AD 512

// ---- device-global scratch (allocation-free rule) ----
__device__ __nv_bfloat16 g_xh [(size_t)AN * AD], g_xl [(size_t)AN * AD];
__device__ __nv_bfloat16 g_Wqh[(size_t)AD * AD], g_Wql[(size_t)AD * AD];
__device__ __nv_bfloat16 g_Wkh[(size_t)AD * AD], g_Wkl[(size_t)AD * AD];
__device__ __nv_bfloat16 g_Wvh[(size_t)AD * AD], g_Wvl[(size_t)AD * AD];
__device__ __nv_bfloat16 g_Qh [(size_t)AN * AD], g_Ql [(size_t)AN * AD];
__device__ __nv_bfloat16 g_Kh [(size_t)AN * AD], g_Kl [(size_t)AN * AD];
__device__ __nv_bfloat16 g_Vth[(size_t)AD * AN], g_Vtl[(size_t)AD * AN];
__device__ __nv_bfloat16 g_Ph [(size_t)AN * (size_t)AN], g_Pl [(size_t)AN * (size_t)AN];
__device__ float         g_S  [(size_t)AN * (size_t)AN];   // fallback attn scratch

// ---------------------------------------------------------------------------
// helpers
// ---------------------------------------------------------------------------
__device__ __forceinline__ uint32_t smem_u32(const void* p) {
    uint32_t a;
    asm("{ .reg .u64 t; cvta.to.shared.u64 t, %1; cvt.u32.u64 %0, t; }"
        : "=r"(a) : "l"(p));
    return a;
}
__device__ __forceinline__ void cp16(uint32_t dst, const void* src) {
    asm volatile("cp.async.cg.shared.global [%0], [%1], 16;" :: "r"(dst), "l"(src));
}
#define CP_COMMIT() asm volatile("cp.async.commit_group;" ::: "memory")
#define CP_WAIT(N)  asm volatile("cp.async.wait_group %0;" :: "n"(N) : "memory")

__device__ __forceinline__ void ldsm_x4(uint32_t* r, uint32_t addr) {
    asm volatile("ldmatrix.sync.aligned.m8n8.x4.shared.b16 {%0,%1,%2,%3}, [%4];"
                 : "=r"(r[0]), "=r"(r[1]), "=r"(r[2]), "=r"(r[3]) : "r"(addr));
}
__device__ __forceinline__ void mma16816(float* d, const uint32_t* a, const uint32_t* b) {
    asm volatile(
        "mma.sync.aligned.m16n8k16.row.col.f32.bf16.bf16.f32 "
        "{%0,%1,%2,%3}, {%4,%5,%6,%7}, {%8,%9}, {%0,%1,%2,%3};"
        : "+f"(d[0]), "+f"(d[1]), "+f"(d[2]), "+f"(d[3])
        : "r"(a[0]), "r"(a[1]), "r"(a[2]), "r"(a[3]), "r"(b[0]), "r"(b[1]));
}
__device__ __forceinline__ void split1(float v, __nv_bfloat16& h, __nv_bfloat16& l) {
    h = __float2bfloat16_rn(v);
    l = __float2bfloat16_rn(v - __bfloat162float(h));
}

// 128B-row swizzle: 16B chunks c in 0..7, phys chunk = c ^ (row & 7).
__device__ __forceinline__ uint32_t swz(uint32_t row, uint32_t c) {
    return row * 128 + ((c ^ (row & 7)) << 4);
}

// ---------------------------------------------------------------------------
// split kernel: fp32 -> (hi, lo) bf16
// ---------------------------------------------------------------------------
__global__ __launch_bounds__(256)
void split_f32(const float* __restrict__ in, __nv_bfloat16* __restrict__ hi,
               __nv_bfloat16* __restrict__ lo, int n4)
{
    int i = blockIdx.x * 256 + threadIdx.x;
    if (i >= n4) return;
    float4 v = *(const float4*)(in + (size_t)i * 4);
    __nv_bfloat16 h0, h1, h2, h3, l0, l1, l2, l3;
    split1(v.x, h0, l0); split1(v.y, h1, l1);
    split1(v.z, h2, l2); split1(v.w, h3, l3);
    *(__nv_bfloat162*)(hi + (size_t)i * 4)     = __nv_bfloat162(h0, h1);
    *(__nv_bfloat162*)(hi + (size_t)i * 4 + 2) = __nv_bfloat162(h2, h3);
    *(__nv_bfloat162*)(lo + (size_t)i * 4)     = __nv_bfloat162(l0, l1);
    *(__nv_bfloat162*)(lo + (size_t)i * 4 + 2) = __nv_bfloat162(l2, l3);
}

// ---------------------------------------------------------------------------
// NT split-bf16 GEMM v5: C[M,Nn] = (Ah+Al)[M,K] * (Bh+Bl)[Nn,K]^T
// Block 128x256x64, 512 threads, warp tile 32x64 (4m x 4n warps), 2-stage.
// EPI: 0 = split bf16 out (Chi/Clo), 1 = mask+scale fp32, 2 = fp32
// ---------------------------------------------------------------------------
#define A_MAT  (128 * 128)                 // 16384 B (128 rows x 128B)
#define B_MAT  (256 * 128)                 // 32768 B (256 rows x 128B)
#define STAGEB (2 * A_MAT + 2 * B_MAT)     // 98304 B (Ah|Al|Bh|Bl)
#define SMEM_TOT (2 * STAGEB)              // 196608 B

template <int EPI>
__global__ __launch_bounds__(512)
void hgemm_nt(const __nv_bfloat16* __restrict__ Ah, const __nv_bfloat16* __restrict__ Al,
              const __nv_bfloat16* __restrict__ Bh, const __nv_bfloat16* __restrict__ Bl,
              int M, int Nn, int K,
              float* __restrict__ Cf,
              __nv_bfloat16* __restrict__ Chi, __nv_bfloat16* __restrict__ Clo,
              const int* __restrict__ mask, float scale)
{
    extern __shared__ char smem[];
    const uint32_t sb = smem_u32(smem);
    const int tid = threadIdx.x;
    const int wid = tid >> 5, lid = tid & 31;
    const int mBase = blockIdx.y * 128;
    const int nBase = blockIdx.x * 256;
    const int mW = (wid & 3) * 32;       // warp m offset (0..96)
    const int nW = (wid >> 2) * 64;      // warp n offset (0,64,128,192)

    const __nv_bfloat16* gA[2] = { Ah + (size_t)mBase * K, Al + (size_t)mBase * K };
    const __nv_bfloat16* gB[2] = { Bh + (size_t)nBase * K, Bl + (size_t)nBase * K };

    float acc[2][8][4];
#pragma unroll
    for (int i = 0; i < 2; i++)
#pragma unroll
        for (int j = 0; j < 8; j++)
#pragma unroll
            for (int v = 0; v < 4; v++) acc[i][j][v] = 0.f;

    const int ntiles = K / 64;

    // A: 128x8=1024 slots (2/thread); B: 256x8=2048 slots (4/thread)
    auto load_tile = [&](int kt, int s) {
        const uint32_t st = sb + s * STAGEB;
#pragma unroll
        for (int j = 0; j < 2; ++j) {
            int slot = tid + j * 512;
            int row = slot >> 3, c = slot & 7;
            size_t go = (size_t)row * K + kt * 64 + c * 8;
            uint32_t so = swz(row, c);
            cp16(st + 0 * A_MAT + so, gA[0] + go);
            cp16(st + 1 * A_MAT + so, gA[1] + go);
        }
#pragma unroll
        for (int j = 0; j < 4; ++j) {
            int slot = tid + j * 512;
            int row = slot >> 3, c = slot & 7;
            size_t go = (size_t)row * K + kt * 64 + c * 8;
            uint32_t so = swz(row, c);
            cp16(st + 2 * A_MAT + so,         gB[0] + go);
            cp16(st + 2 * A_MAT + B_MAT + so, gB[1] + go);
        }
        CP_COMMIT();
    };

    load_tile(0, 0);

    for (int kt = 0; kt < ntiles; ++kt) {
        if (kt + 1 < ntiles) {
            load_tile(kt + 1, (kt + 1) & 1);
            CP_WAIT(1);
        } else {
            CP_WAIT(0);
        }
        __syncthreads();

        const uint32_t st = sb + (kt & 1) * STAGEB;

#pragma unroll
        for (int s = 0; s < 4; ++s) {       // 4 x k16 within the 64-k tile
            uint32_t ah[2][4], al[2][4];
            const uint32_t cA = s * 2 + (lid >> 4);
#pragma unroll
            for (int f = 0; f < 2; ++f) {
                uint32_t ra = st + swz(mW + f * 16 + (lid & 15), cA);
                ldsm_x4(ah[f], ra);
                ldsm_x4(al[f], ra + A_MAT);
            }
            const uint32_t rowB = ((lid >> 4) * 8) + (lid & 7);
            const uint32_t cB = s * 2 + ((lid >> 3) & 1);
            // process B in two 32-col halves to bound live registers
#pragma unroll
            for (int half = 0; half < 2; ++half) {
                uint32_t bh[4][2], bl[4][2];
#pragma unroll
                for (int f = 0; f < 2; ++f) {
                    uint32_t rb = st + 2 * A_MAT +
                                  swz(nW + half * 32 + f * 16 + rowB, cB);
                    ldsm_x4(&bh[2 * f][0], rb);
                    ldsm_x4(&bl[2 * f][0], rb + B_MAT);
                }
#pragma unroll
                for (int mf = 0; mf < 2; ++mf)
#pragma unroll
                    for (int nf = 0; nf < 4; ++nf) {
                        float* d = acc[mf][half * 4 + nf];
                        mma16816(d, ah[mf], bh[nf]);
                        mma16816(d, ah[mf], bl[nf]);
                        mma16816(d, al[mf], bh[nf]);
                    }
            }
        }
        __syncthreads();
    }

    // ---- epilogue ----
    const int r0b = mBase + mW + (lid >> 2);
    const int c0b = nBase + nW + (lid & 3) * 2;
#pragma unroll
    for (int mf = 0; mf < 2; ++mf) {
#pragma unroll
        for (int nf = 0; nf < 8; ++nf) {
            const float* d = acc[mf][nf];
#pragma unroll
            for (int h = 0; h < 2; ++h) {
                int row = r0b + mf * 16 + h * 8;
                int col = c0b + nf * 8;
                size_t o = (size_t)row * Nn + col;
                float v0 = d[h * 2 + 0], v1 = d[h * 2 + 1];
                if (EPI == 0) {
                    __nv_bfloat16 h0, h1, l0, l1;
                    split1(v0, h0, l0); split1(v1, h1, l1);
                    *(__nv_bfloat162*)(Chi + o) = __nv_bfloat162(h0, h1);
                    *(__nv_bfloat162*)(Clo + o) = __nv_bfloat162(l0, l1);
                } else if (EPI == 1) {
                    int2 mv = *(const int2*)(mask + o);
                    float2 w;
                    w.x = mv.x ? -1e9f : v0 * scale;
                    w.y = mv.y ? -1e9f : v1 * scale;
                    *(float2*)(Cf + o) = w;
                } else {
                    *(float2*)(Cf + o) = make_float2(v0, v1);
                }
            }
        }
    }
}

// ---------------------------------------------------------------------------
// Row softmax (in place, fp32) + emit P hi/lo bf16.
// ---------------------------------------------------------------------------
__global__ __launch_bounds__(256)
void softmax_rows(float* __restrict__ S, __nv_bfloat16* __restrict__ Ph,
                  __nv_bfloat16* __restrict__ Pl, int n)
{
    extern __shared__ float row[];
    __shared__ float red[33];

    const int tid = threadIdx.x;
    float* p = S + (size_t)blockIdx.x * n;
    __nv_bfloat16* ph = Ph + (size_t)blockIdx.x * n;
    __nv_bfloat16* pl = Pl + (size_t)blockIdx.x * n;

    float m = -INFINITY;
    for (int i = tid * 4; i < n; i += 1024) {
        float4 v = *(const float4*)(p + i);
        *(float4*)(row + i) = v;
        m = fmaxf(m, fmaxf(fmaxf(v.x, v.y), fmaxf(v.z, v.w)));
    }
#pragma unroll
    for (int o = 16; o; o >>= 1) m = fmaxf(m, __shfl_xor_sync(~0u, m, o));
    if ((tid & 31) == 0) red[tid >> 5] = m;
    __syncthreads();
    if (tid < 32) {
        float v = (tid < 8) ? red[tid] : -INFINITY;
#pragma unroll
        for (int o = 4; o; o >>= 1) v = fmaxf(v, __shfl_xor_sync(~0u, v, o));
        if (tid == 0) red[32] = v;
    }
    __syncthreads();
    m = red[32];

    float s = 0.f;
    for (int i = tid * 4; i < n; i += 1024) {
        float4 v = *(float4*)(row + i);
        v.x = __expf(v.x - m); v.y = __expf(v.y - m);
        v.z = __expf(v.z - m); v.w = __expf(v.w - m);
        s += (v.x + v.y) + (v.z + v.w);
        *(float4*)(row + i) = v;
    }
    __syncthreads();
#pragma unroll
    for (int o = 16; o; o >>= 1) s += __shfl_xor_sync(~0u, s, o);
    if ((tid & 31) == 0) red[tid >> 5] = s;
    __syncthreads();
    if (tid < 32) {
        float v = (tid < 8) ? red[tid] : 0.f;
#pragma unroll
        for (int o = 4; o; o >>= 1) v += __shfl_xor_sync(~0u, v, o);
        if (tid == 0) red[32] = v;
    }
    __syncthreads();
    const float inv = 1.f / red[32];

    for (int i = tid * 4; i < n; i += 1024) {
        float4 v = *(float4*)(row + i);
        v.x *= inv; v.y *= inv; v.z *= inv; v.w *= inv;
        *(float4*)(p + i) = v;
        __nv_bfloat16 h0, h1, h2, h3, l0, l1, l2, l3;
        split1(v.x, h0, l0); split1(v.y, h1, l1);
        split1(v.z, h2, l2); split1(v.w, h3, l3);
        *(__nv_bfloat162*)(ph + i)     = __nv_bfloat162(h0, h1);
        *(__nv_bfloat162*)(ph + i + 2) = __nv_bfloat162(h2, h3);
        *(__nv_bfloat162*)(pl + i)     = __nv_bfloat162(l0, l1);
        *(__nv_bfloat162*)(pl + i + 2) = __nv_bfloat162(l2, l3);
    }
}

// ---------------------------------------------------------------------------
// Launch
// ---------------------------------------------------------------------------
extern "C" void kernel_launch(void* const* d_in, const int* in_sizes, int n_in,
                              void* d_out, int out_size)
{
    const float* x    = (const float*)d_in[0];
    const int*   mask = (const int*)d_in[1];
    const float* Wq   = (const float*)d_in[2];
    const float* Wk   = (const float*)d_in[3];
    const float* Wv   = (const float*)d_in[4];
    float* out = (float*)d_out;

    __nv_bfloat16 *xh, *xl, *Wqh, *Wql, *Wkh, *Wkl, *Wvh, *Wvl;
    __nv_bfloat16 *Qh, *Ql, *Kh, *Kl, *Vth, *Vtl, *Ph, *Pl;
    cudaGetSymbolAddress((void**)&xh,  g_xh);  cudaGetSymbolAddress((void**)&xl,  g_xl);
    cudaGetSymbolAddress((void**)&Wqh, g_Wqh); cudaGetSymbolAddress((void**)&Wql, g_Wql);
    cudaGetSymbolAddress((void**)&Wkh, g_Wkh); cudaGetSymbolAddress((void**)&Wkl, g_Wkl);
    cudaGetSymbolAddress((void**)&Wvh, g_Wvh); cudaGetSymbolAddress((void**)&Wvl, g_Wvl);
    cudaGetSymbolAddress((void**)&Qh,  g_Qh);  cudaGetSymbolAddress((void**)&Ql,  g_Ql);
    cudaGetSymbolAddress((void**)&Kh,  g_Kh);  cudaGetSymbolAddress((void**)&Kl,  g_Kl);
    cudaGetSymbolAddress((void**)&Vth, g_Vth); cudaGetSymbolAddress((void**)&Vtl, g_Vtl);
    cudaGetSymbolAddress((void**)&Ph,  g_Ph);  cudaGetSymbolAddress((void**)&Pl,  g_Pl);

    const size_t nd = (size_t)AN * AD;
    const size_t nn = (size_t)AN * AN;
    float* cntx = out;
    float* attn = out + nd;
    if ((size_t)out_size < nd + nn)
        cudaGetSymbolAddress((void**)&attn, g_S);

    const float scale = 1.0f / sqrtf((float)AD);

    cudaFuncSetAttribute(hgemm_nt<0>, cudaFuncAttributeMaxDynamicSharedMemorySize, SMEM_TOT);
    cudaFuncSetAttribute(hgemm_nt<1>, cudaFuncAttributeMaxDynamicSharedMemorySize, SMEM_TOT);
    cudaFuncSetAttribute(hgemm_nt<2>, cudaFuncAttributeMaxDynamicSharedMemorySize, SMEM_TOT);

    // 1) split inputs
    split_f32<<<(AN * AD / 4 + 255) / 256, 256>>>(x,  xh,  xl,  AN * AD / 4);
    split_f32<<<(AD * AD / 4 + 255) / 256, 256>>>(Wq, Wqh, Wql, AD * AD / 4);
    split_f32<<<(AD * AD / 4 + 255) / 256, 256>>>(Wk, Wkh, Wkl, AD * AD / 4);
    split_f32<<<(AD * AD / 4 + 255) / 256, 256>>>(Wv, Wvh, Wvl, AD * AD / 4);

    // 2) projections (split epilogue)  [grid = (Nn/256, M/128)]
    dim3 gP(AD / 256, AN / 128);
    hgemm_nt<0><<<gP, 512, SMEM_TOT>>>(xh, xl, Wqh, Wql, AN, AD, AD,
                                       nullptr, Qh, Ql, nullptr, 1.f);
    hgemm_nt<0><<<gP, 512, SMEM_TOT>>>(xh, xl, Wkh, Wkl, AN, AD, AD,
                                       nullptr, Kh, Kl, nullptr, 1.f);
    dim3 gV(AN / 256, AD / 128);
    hgemm_nt<0><<<gV, 512, SMEM_TOT>>>(Wvh, Wvl, xh, xl, AD, AN, AD,
                                       nullptr, Vth, Vtl, nullptr, 1.f);

    // 3) scores (mask epilogue, fp32)
    dim3 gS(AN / 256, AN / 128);
    hgemm_nt<1><<<gS, 512, SMEM_TOT>>>(Qh, Ql, Kh, Kl, AN, AN, AD,
                                       attn, nullptr, nullptr, mask, scale);

    // 4) softmax (+ P hi/lo)
    softmax_rows<<<AN, 256, AN * sizeof(float)>>>(attn, Ph, Pl, AN);

    // 5) context (fp32 epilogue)
    dim3 gC(AD / 256, AN / 128);
    hgemm_nt<2><<<gC, 512, SMEM_TOT>>>(Ph, Pl, Vth, Vtl, AN, AD, AN,
                                       cntx, nullptr, nullptr, nullptr, 1.f);
}

// round 13
// speedup vs baseline: 1.4103x; 1.1634x over previous
#include <cuda_runtime.h>
#include <cuda_bf16.h>
#include <cuda_fp16.h>
#include <math.h>
#include <stdint.h>

// ============================================================================
// LocalAttention, split-precision warp MMA.
//   split x,W -> hi/lo bf16
//   Q = x@Wq^T, K = x@Wk^T (bf16 3-pass, split-bf16 epi)
//   Vt = Wv@x^T            (bf16 3-pass, split-fp16 epi)
//   attn = softmax(mask ? -1e9 : Q@K^T*s)  (bf16 3-pass, mask epi; fp32)
//   softmax emits P as single fp16
//   cntx = P @ Vt^T        (fp16 2-pass: P unsplit, Vt hi/lo)
// Output: [cntx (N*D) | attn (N*N)].  Mask is int32.
// ============================================================================

#define AN 8192
#define AD 512

// ---- device-global scratch ----
__device__ __nv_bfloat16 g_xh [(size_t)AN * AD], g_xl [(size_t)AN * AD];
__device__ __nv_bfloat16 g_Wqh[(size_t)AD * AD], g_Wql[(size_t)AD * AD];
__device__ __nv_bfloat16 g_Wkh[(size_t)AD * AD], g_Wkl[(size_t)AD * AD];
__device__ __nv_bfloat16 g_Wvh[(size_t)AD * AD], g_Wvl[(size_t)AD * AD];
__device__ __nv_bfloat16 g_Qh [(size_t)AN * AD], g_Ql [(size_t)AN * AD];
__device__ __nv_bfloat16 g_Kh [(size_t)AN * AD], g_Kl [(size_t)AN * AD];
__device__ __half        g_Vth[(size_t)AD * AN], g_Vtl[(size_t)AD * AN];
__device__ __half        g_P  [(size_t)AN * (size_t)AN];
__device__ float         g_S  [(size_t)AN * (size_t)AN];   // fallback attn scratch

// ---------------------------------------------------------------------------
// helpers
// ---------------------------------------------------------------------------
__device__ __forceinline__ uint32_t smem_u32(const void* p) {
    uint32_t a;
    asm("{ .reg .u64 t; cvta.to.shared.u64 t, %1; cvt.u32.u64 %0, t; }"
        : "=r"(a) : "l"(p));
    return a;
}
__device__ __forceinline__ void cp16(uint32_t dst, const void* src) {
    asm volatile("cp.async.cg.shared.global [%0], [%1], 16;" :: "r"(dst), "l"(src));
}
#define CP_COMMIT() asm volatile("cp.async.commit_group;" ::: "memory")
#define CP_WAIT(N)  asm volatile("cp.async.wait_group %0;" :: "n"(N) : "memory")

__device__ __forceinline__ void ldsm_x4(uint32_t* r, uint32_t addr) {
    asm volatile("ldmatrix.sync.aligned.m8n8.x4.shared.b16 {%0,%1,%2,%3}, [%4];"
                 : "=r"(r[0]), "=r"(r[1]), "=r"(r[2]), "=r"(r[3]) : "r"(addr));
}
__device__ __forceinline__ void mma16816(float* d, const uint32_t* a, const uint32_t* b) {
    asm volatile(
        "mma.sync.aligned.m16n8k16.row.col.f32.bf16.bf16.f32 "
        "{%0,%1,%2,%3}, {%4,%5,%6,%7}, {%8,%9}, {%0,%1,%2,%3};"
        : "+f"(d[0]), "+f"(d[1]), "+f"(d[2]), "+f"(d[3])
        : "r"(a[0]), "r"(a[1]), "r"(a[2]), "r"(a[3]), "r"(b[0]), "r"(b[1]));
}
__device__ __forceinline__ void mma16816h(float* d, const uint32_t* a, const uint32_t* b) {
    asm volatile(
        "mma.sync.aligned.m16n8k16.row.col.f32.f16.f16.f32 "
        "{%0,%1,%2,%3}, {%4,%5,%6,%7}, {%8,%9}, {%0,%1,%2,%3};"
        : "+f"(d[0]), "+f"(d[1]), "+f"(d[2]), "+f"(d[3])
        : "r"(a[0]), "r"(a[1]), "r"(a[2]), "r"(a[3]), "r"(b[0]), "r"(b[1]));
}
__device__ __forceinline__ void split1(float v, __nv_bfloat16& h, __nv_bfloat16& l) {
    h = __float2bfloat16_rn(v);
    l = __float2bfloat16_rn(v - __bfloat162float(h));
}
__device__ __forceinline__ void split1h(float v, __half& h, __half& l) {
    h = __float2half_rn(v);
    l = __float2half_rn(v - __half2float(h));
}

// 128B-row swizzle: 16B chunks c in 0..7, phys chunk = c ^ (row & 7).
__device__ __forceinline__ uint32_t swz(uint32_t row, uint32_t c) {
    return row * 128 + ((c ^ (row & 7)) << 4);
}

// ---------------------------------------------------------------------------
// split kernel: fp32 -> (hi, lo) bf16
// ---------------------------------------------------------------------------
__global__ __launch_bounds__(256)
void split_f32(const float* __restrict__ in, __nv_bfloat16* __restrict__ hi,
               __nv_bfloat16* __restrict__ lo, int n4)
{
    int i = blockIdx.x * 256 + threadIdx.x;
    if (i >= n4) return;
    float4 v = *(const float4*)(in + (size_t)i * 4);
    __nv_bfloat16 h0, h1, h2, h3, l0, l1, l2, l3;
    split1(v.x, h0, l0); split1(v.y, h1, l1);
    split1(v.z, h2, l2); split1(v.w, h3, l3);
    *(__nv_bfloat162*)(hi + (size_t)i * 4)     = __nv_bfloat162(h0, h1);
    *(__nv_bfloat162*)(hi + (size_t)i * 4 + 2) = __nv_bfloat162(h2, h3);
    *(__nv_bfloat162*)(lo + (size_t)i * 4)     = __nv_bfloat162(l0, l1);
    *(__nv_bfloat162*)(lo + (size_t)i * 4 + 2) = __nv_bfloat162(l2, l3);
}

// ---------------------------------------------------------------------------
// NT split-bf16 GEMM (3-pass): C = (Ah+Al)(Bh+Bl)^T.  Block 128x256x64,
// 512 threads, warp tile 32x64, 2-stage cp.async.
// EPI: 0 = split-bf16 out, 1 = mask+scale fp32, 2 = fp32, 3 = split-fp16 out
// ---------------------------------------------------------------------------
#define A_MAT  (128 * 128)
#define B_MAT  (256 * 128)
#define STAGEB (2 * A_MAT + 2 * B_MAT)     // 98304 B
#define SMEM_TOT (2 * STAGEB)              // 196608 B

template <int EPI>
__global__ __launch_bounds__(512)
void hgemm_nt(const __nv_bfloat16* __restrict__ Ah, const __nv_bfloat16* __restrict__ Al,
              const __nv_bfloat16* __restrict__ Bh, const __nv_bfloat16* __restrict__ Bl,
              int M, int Nn, int K,
              float* __restrict__ Cf,
              __nv_bfloat16* __restrict__ Chi, __nv_bfloat16* __restrict__ Clo,
              __half* __restrict__ Fhi, __half* __restrict__ Flo,
              const int* __restrict__ mask, float scale)
{
    extern __shared__ char smem[];
    const uint32_t sb = smem_u32(smem);
    const int tid = threadIdx.x;
    const int wid = tid >> 5, lid = tid & 31;
    const int mBase = blockIdx.y * 128;
    const int nBase = blockIdx.x * 256;
    const int mW = (wid & 3) * 32;
    const int nW = (wid >> 2) * 64;

    const __nv_bfloat16* gA[2] = { Ah + (size_t)mBase * K, Al + (size_t)mBase * K };
    const __nv_bfloat16* gB[2] = { Bh + (size_t)nBase * K, Bl + (size_t)nBase * K };

    float acc[2][8][4];
#pragma unroll
    for (int i = 0; i < 2; i++)
#pragma unroll
        for (int j = 0; j < 8; j++)
#pragma unroll
            for (int v = 0; v < 4; v++) acc[i][j][v] = 0.f;

    const int ntiles = K / 64;

    auto load_tile = [&](int kt, int s) {
        const uint32_t st = sb + s * STAGEB;
#pragma unroll
        for (int j = 0; j < 2; ++j) {
            int slot = tid + j * 512;
            int row = slot >> 3, c = slot & 7;
            size_t go = (size_t)row * K + kt * 64 + c * 8;
            uint32_t so = swz(row, c);
            cp16(st + 0 * A_MAT + so, gA[0] + go);
            cp16(st + 1 * A_MAT + so, gA[1] + go);
        }
#pragma unroll
        for (int j = 0; j < 4; ++j) {
            int slot = tid + j * 512;
            int row = slot >> 3, c = slot & 7;
            size_t go = (size_t)row * K + kt * 64 + c * 8;
            uint32_t so = swz(row, c);
            cp16(st + 2 * A_MAT + so,         gB[0] + go);
            cp16(st + 2 * A_MAT + B_MAT + so, gB[1] + go);
        }
        CP_COMMIT();
    };

    load_tile(0, 0);

    for (int kt = 0; kt < ntiles; ++kt) {
        if (kt + 1 < ntiles) {
            load_tile(kt + 1, (kt + 1) & 1);
            CP_WAIT(1);
        } else {
            CP_WAIT(0);
        }
        __syncthreads();

        const uint32_t st = sb + (kt & 1) * STAGEB;

#pragma unroll
        for (int s = 0; s < 4; ++s) {
            uint32_t ah[2][4], al[2][4];
            const uint32_t cA = s * 2 + (lid >> 4);
#pragma unroll
            for (int f = 0; f < 2; ++f) {
                uint32_t ra = st + swz(mW + f * 16 + (lid & 15), cA);
                ldsm_x4(ah[f], ra);
                ldsm_x4(al[f], ra + A_MAT);
            }
            const uint32_t rowB = ((lid >> 4) * 8) + (lid & 7);
            const uint32_t cB = s * 2 + ((lid >> 3) & 1);
#pragma unroll
            for (int half = 0; half < 2; ++half) {
                uint32_t bh[4][2], bl[4][2];
#pragma unroll
                for (int f = 0; f < 2; ++f) {
                    uint32_t rb = st + 2 * A_MAT +
                                  swz(nW + half * 32 + f * 16 + rowB, cB);
                    ldsm_x4(&bh[2 * f][0], rb);
                    ldsm_x4(&bl[2 * f][0], rb + B_MAT);
                }
#pragma unroll
                for (int mf = 0; mf < 2; ++mf)
#pragma unroll
                    for (int nf = 0; nf < 4; ++nf) {
                        float* d = acc[mf][half * 4 + nf];
                        mma16816(d, ah[mf], bh[nf]);
                        mma16816(d, ah[mf], bl[nf]);
                        mma16816(d, al[mf], bh[nf]);
                    }
            }
        }
        __syncthreads();
    }

    // ---- epilogue ----
    const int r0b = mBase + mW + (lid >> 2);
    const int c0b = nBase + nW + (lid & 3) * 2;
#pragma unroll
    for (int mf = 0; mf < 2; ++mf) {
#pragma unroll
        for (int nf = 0; nf < 8; ++nf) {
            const float* d = acc[mf][nf];
#pragma unroll
            for (int h = 0; h < 2; ++h) {
                int row = r0b + mf * 16 + h * 8;
                int col = c0b + nf * 8;
                size_t o = (size_t)row * Nn + col;
                float v0 = d[h * 2 + 0], v1 = d[h * 2 + 1];
                if (EPI == 0) {
                    __nv_bfloat16 h0, h1, l0, l1;
                    split1(v0, h0, l0); split1(v1, h1, l1);
                    *(__nv_bfloat162*)(Chi + o) = __nv_bfloat162(h0, h1);
                    *(__nv_bfloat162*)(Clo + o) = __nv_bfloat162(l0, l1);
                } else if (EPI == 1) {
                    int2 mv = *(const int2*)(mask + o);
                    float2 w;
                    w.x = mv.x ? -1e9f : v0 * scale;
                    w.y = mv.y ? -1e9f : v1 * scale;
                    *(float2*)(Cf + o) = w;
                } else if (EPI == 2) {
                    *(float2*)(Cf + o) = make_float2(v0, v1);
                } else {
                    __half h0, h1, l0, l1;
                    split1h(v0, h0, l0); split1h(v1, h1, l1);
                    *(__half2*)(Fhi + o) = __halves2half2(h0, h1);
                    *(__half2*)(Flo + o) = __halves2half2(l0, l1);
                }
            }
        }
    }
}

// ---------------------------------------------------------------------------
// NT fp16 2-pass GEMM: C[M,Nn] = A[M,K] * (Bh+Bl)[Nn,K]^T, fp32 out.
// A unsplit fp16. Block 128x256x64, 512 threads, warp tile 32x64, 2-stage.
// ---------------------------------------------------------------------------
#define STAGE2 (A_MAT + 2 * B_MAT)         // 81920 B (A|Bh|Bl)
#define SMEM2_TOT (2 * STAGE2)             // 163840 B

__global__ __launch_bounds__(512)
void hgemm2_f16(const __half* __restrict__ A,
                const __half* __restrict__ Bh, const __half* __restrict__ Bl,
                int M, int Nn, int K, float* __restrict__ Cf)
{
    extern __shared__ char smem[];
    const uint32_t sb = smem_u32(smem);
    const int tid = threadIdx.x;
    const int wid = tid >> 5, lid = tid & 31;
    const int mBase = blockIdx.y * 128;
    const int nBase = blockIdx.x * 256;
    const int mW = (wid & 3) * 32;
    const int nW = (wid >> 2) * 64;

    const __half* gA = A + (size_t)mBase * K;
    const __half* gB[2] = { Bh + (size_t)nBase * K, Bl + (size_t)nBase * K };

    float acc[2][8][4];
#pragma unroll
    for (int i = 0; i < 2; i++)
#pragma unroll
        for (int j = 0; j < 8; j++)
#pragma unroll
            for (int v = 0; v < 4; v++) acc[i][j][v] = 0.f;

    const int ntiles = K / 64;

    auto load_tile = [&](int kt, int s) {
        const uint32_t st = sb + s * STAGE2;
#pragma unroll
        for (int j = 0; j < 2; ++j) {
            int slot = tid + j * 512;
            int row = slot >> 3, c = slot & 7;
            size_t go = (size_t)row * K + kt * 64 + c * 8;
            cp16(st + swz(row, c), gA + go);
        }
#pragma unroll
        for (int j = 0; j < 4; ++j) {
            int slot = tid + j * 512;
            int row = slot >> 3, c = slot & 7;
            size_t go = (size_t)row * K + kt * 64 + c * 8;
            uint32_t so = swz(row, c);
            cp16(st + A_MAT + so,         gB[0] + go);
            cp16(st + A_MAT + B_MAT + so, gB[1] + go);
        }
        CP_COMMIT();
    };

    load_tile(0, 0);

    for (int kt = 0; kt < ntiles; ++kt) {
        if (kt + 1 < ntiles) {
            load_tile(kt + 1, (kt + 1) & 1);
            CP_WAIT(1);
        } else {
            CP_WAIT(0);
        }
        __syncthreads();

        const uint32_t st = sb + (kt & 1) * STAGE2;

#pragma unroll
        for (int s = 0; s < 4; ++s) {
            uint32_t ah[2][4];
            const uint32_t cA = s * 2 + (lid >> 4);
#pragma unroll
            for (int f = 0; f < 2; ++f)
                ldsm_x4(ah[f], st + swz(mW + f * 16 + (lid & 15), cA));

            const uint32_t rowB = ((lid >> 4) * 8) + (lid & 7);
            const uint32_t cB = s * 2 + ((lid >> 3) & 1);
#pragma unroll
            for (int half = 0; half < 2; ++half) {
                uint32_t bh[4][2], bl[4][2];
#pragma unroll
                for (int f = 0; f < 2; ++f) {
                    uint32_t rb = st + A_MAT +
                                  swz(nW + half * 32 + f * 16 + rowB, cB);
                    ldsm_x4(&bh[2 * f][0], rb);
                    ldsm_x4(&bl[2 * f][0], rb + B_MAT);
                }
#pragma unroll
                for (int mf = 0; mf < 2; ++mf)
#pragma unroll
                    for (int nf = 0; nf < 4; ++nf) {
                        float* d = acc[mf][half * 4 + nf];
                        mma16816h(d, ah[mf], bh[nf]);
                        mma16816h(d, ah[mf], bl[nf]);
                    }
            }
        }
        __syncthreads();
    }

    const int r0b = mBase + mW + (lid >> 2);
    const int c0b = nBase + nW + (lid & 3) * 2;
#pragma unroll
    for (int mf = 0; mf < 2; ++mf)
#pragma unroll
        for (int nf = 0; nf < 8; ++nf) {
            const float* d = acc[mf][nf];
#pragma unroll
            for (int h = 0; h < 2; ++h) {
                int row = r0b + mf * 16 + h * 8;
                int col = c0b + nf * 8;
                *(float2*)(Cf + (size_t)row * Nn + col) =
                    make_float2(d[h * 2 + 0], d[h * 2 + 1]);
            }
        }
}

// ---------------------------------------------------------------------------
// Row softmax (in place, fp32) + emit P as single fp16.
// ---------------------------------------------------------------------------
__global__ __launch_bounds__(256)
void softmax_rows(float* __restrict__ S, __half* __restrict__ P, int n)
{
    extern __shared__ float row[];
    __shared__ float red[33];

    const int tid = threadIdx.x;
    float* p = S + (size_t)blockIdx.x * n;
    __half* ph = P + (size_t)blockIdx.x * n;

    float m = -INFINITY;
    for (int i = tid * 4; i < n; i += 1024) {
        float4 v = *(const float4*)(p + i);
        *(float4*)(row + i) = v;
        m = fmaxf(m, fmaxf(fmaxf(v.x, v.y), fmaxf(v.z, v.w)));
    }
#pragma unroll
    for (int o = 16; o; o >>= 1) m = fmaxf(m, __shfl_xor_sync(~0u, m, o));
    if ((tid & 31) == 0) red[tid >> 5] = m;
    __syncthreads();
    if (tid < 32) {
        float v = (tid < 8) ? red[tid] : -INFINITY;
#pragma unroll
        for (int o = 4; o; o >>= 1) v = fmaxf(v, __shfl_xor_sync(~0u, v, o));
        if (tid == 0) red[32] = v;
    }
    __syncthreads();
    m = red[32];

    float s = 0.f;
    for (int i = tid * 4; i < n; i += 1024) {
        float4 v = *(float4*)(row + i);
        v.x = __expf(v.x - m); v.y = __expf(v.y - m);
        v.z = __expf(v.z - m); v.w = __expf(v.w - m);
        s += (v.x + v.y) + (v.z + v.w);
        *(float4*)(row + i) = v;
    }
    __syncthreads();
#pragma unroll
    for (int o = 16; o; o >>= 1) s += __shfl_xor_sync(~0u, s, o);
    if ((tid & 31) == 0) red[tid >> 5] = s;
    __syncthreads();
    if (tid < 32) {
        float v = (tid < 8) ? red[tid] : 0.f;
#pragma unroll
        for (int o = 4; o; o >>= 1) v += __shfl_xor_sync(~0u, v, o);
        if (tid == 0) red[32] = v;
    }
    __syncthreads();
    const float inv = 1.f / red[32];

    for (int i = tid * 4; i < n; i += 1024) {
        float4 v = *(float4*)(row + i);
        v.x *= inv; v.y *= inv; v.z *= inv; v.w *= inv;
        *(float4*)(p + i) = v;
        *(__half2*)(ph + i)     = __floats2half2_rn(v.x, v.y);
        *(__half2*)(ph + i + 2) = __floats2half2_rn(v.z, v.w);
    }
}

// ---------------------------------------------------------------------------
// Launch
// ---------------------------------------------------------------------------
extern "C" void kernel_launch(void* const* d_in, const int* in_sizes, int n_in,
                              void* d_out, int out_size)
{
    const float* x    = (const float*)d_in[0];
    const int*   mask = (const int*)d_in[1];
    const float* Wq   = (const float*)d_in[2];
    const float* Wk   = (const float*)d_in[3];
    const float* Wv   = (const float*)d_in[4];
    float* out = (float*)d_out;

    __nv_bfloat16 *xh, *xl, *Wqh, *Wql, *Wkh, *Wkl, *Wvh, *Wvl;
    __nv_bfloat16 *Qh, *Ql, *Kh, *Kl;
    __half *Vth, *Vtl, *P;
    cudaGetSymbolAddress((void**)&xh,  g_xh);  cudaGetSymbolAddress((void**)&xl,  g_xl);
    cudaGetSymbolAddress((void**)&Wqh, g_Wqh); cudaGetSymbolAddress((void**)&Wql, g_Wql);
    cudaGetSymbolAddress((void**)&Wkh, g_Wkh); cudaGetSymbolAddress((void**)&Wkl, g_Wkl);
    cudaGetSymbolAddress((void**)&Wvh, g_Wvh); cudaGetSymbolAddress((void**)&Wvl, g_Wvl);
    cudaGetSymbolAddress((void**)&Qh,  g_Qh);  cudaGetSymbolAddress((void**)&Ql,  g_Ql);
    cudaGetSymbolAddress((void**)&Kh,  g_Kh);  cudaGetSymbolAddress((void**)&Kl,  g_Kl);
    cudaGetSymbolAddress((void**)&Vth, g_Vth); cudaGetSymbolAddress((void**)&Vtl, g_Vtl);
    cudaGetSymbolAddress((void**)&P,   g_P);

    const size_t nd = (size_t)AN * AD;
    const size_t nn = (size_t)AN * AN;
    float* cntx = out;
    float* attn = out + nd;
    if ((size_t)out_size < nd + nn)
        cudaGetSymbolAddress((void**)&attn, g_S);

    const float scale = 1.0f / sqrtf((float)AD);

    cudaFuncSetAttribute(hgemm_nt<0>, cudaFuncAttributeMaxDynamicSharedMemorySize, SMEM_TOT);
    cudaFuncSetAttribute(hgemm_nt<1>, cudaFuncAttributeMaxDynamicSharedMemorySize, SMEM_TOT);
    cudaFuncSetAttribute(hgemm_nt<3>, cudaFuncAttributeMaxDynamicSharedMemorySize, SMEM_TOT);
    cudaFuncSetAttribute(hgemm2_f16,  cudaFuncAttributeMaxDynamicSharedMemorySize, SMEM2_TOT);

    // 1) split inputs (bf16 hi/lo)
    split_f32<<<(AN * AD / 4 + 255) / 256, 256>>>(x,  xh,  xl,  AN * AD / 4);
    split_f32<<<(AD * AD / 4 + 255) / 256, 256>>>(Wq, Wqh, Wql, AD * AD / 4);
    split_f32<<<(AD * AD / 4 + 255) / 256, 256>>>(Wk, Wkh, Wkl, AD * AD / 4);
    split_f32<<<(AD * AD / 4 + 255) / 256, 256>>>(Wv, Wvh, Wvl, AD * AD / 4);

    // 2) projections
    dim3 gP(AD / 256, AN / 128);
    hgemm_nt<0><<<gP, 512, SMEM_TOT>>>(xh, xl, Wqh, Wql, AN, AD, AD,
                                       nullptr, Qh, Ql, nullptr, nullptr, nullptr, 1.f);
    hgemm_nt<0><<<gP, 512, SMEM_TOT>>>(xh, xl, Wkh, Wkl, AN, AD, AD,
                                       nullptr, Kh, Kl, nullptr, nullptr, nullptr, 1.f);
    dim3 gV(AN / 256, AD / 128);
    hgemm_nt<3><<<gV, 512, SMEM_TOT>>>(Wvh, Wvl, xh, xl, AD, AN, AD,
                                       nullptr, nullptr, nullptr, Vth, Vtl, nullptr, 1.f);

    // 3) scores (mask epilogue, fp32)
    dim3 gS(AN / 256, AN / 128);
    hgemm_nt<1><<<gS, 512, SMEM_TOT>>>(Qh, Ql, Kh, Kl, AN, AN, AD,
                                       attn, nullptr, nullptr, nullptr, nullptr, mask, scale);

    // 4) softmax (+ fp16 P)
    softmax_rows<<<AN, 256, AN * sizeof(float)>>>(attn, P, AN);

    // 5) context: fp16 2-pass
    dim3 gC(AD / 256, AN / 128);
    hgemm2_f16<<<gC, 512, SMEM2_TOT>>>(P, Vth, Vtl, AN, AD, AN, cntx);
}